// round 1
// baseline (speedup 1.0000x reference)
#include <cuda_runtime.h>

// Problem constants
#define EMBED  1024
#define NHEADS 16
#define HDIM   64
#define BATCH  4
#define SEQ    2048
#define MTOK   (BATCH * SEQ)   // 8192

// Scratch (device globals; no allocation allowed)
__device__ float g_q[BATCH * NHEADS * SEQ * HDIM];     // 32 MB, [B,H,N,D]
__device__ float g_k[BATCH * NHEADS * SEQ * HDIM];
__device__ float g_v[BATCH * NHEADS * SEQ * HDIM];
__device__ float g_attn[MTOK * EMBED];                 // 32 MB, [B,N,E]

// ---------------------------------------------------------------------------
// SGEMM: C[m][n] = sum_k A[m][k] * W[n][k] + bias[n]      (K = 1024 fixed)
// BM=BN=128, BK=16, 256 threads, 8x8 per-thread microtile.
// NEPI==0: QKV epilogue (scatter into g_q/g_k/g_v in [B,H,N,D] layout)
// NEPI==1: plain epilogue, A is g_attn, C = d_out
// ---------------------------------------------------------------------------
template <int NEPI>
__global__ __launch_bounds__(256) void gemm128(
    const float* __restrict__ A, const float* __restrict__ W,
    const float* __restrict__ bias, float* __restrict__ C)
{
    __shared__ float As[16][132];
    __shared__ float Bs[16][132];

    const int tid = threadIdx.x;
    const int ty  = tid >> 4;        // 0..15
    const int tx  = tid & 15;        // 0..15
    const int m0  = blockIdx.y * 128;
    const int n0  = blockIdx.x * 128;
    const int lr  = tid >> 2;        // 0..63
    const int lc  = (tid & 3) << 2;  // 0,4,8,12

    const float* Abase = (NEPI == 1) ? (const float*)g_attn : A;
    const float* Aptr  = Abase + (size_t)m0 * EMBED;
    const float* Wptr  = W     + (size_t)n0 * EMBED;

    float acc[8][8];
#pragma unroll
    for (int i = 0; i < 8; i++)
#pragma unroll
        for (int j = 0; j < 8; j++) acc[i][j] = 0.f;

    for (int k0 = 0; k0 < EMBED; k0 += 16) {
#pragma unroll
        for (int h = 0; h < 2; h++) {
            int r = lr + h * 64;
            float4 va = *(const float4*)(Aptr + (size_t)r * EMBED + k0 + lc);
            As[lc + 0][r] = va.x; As[lc + 1][r] = va.y;
            As[lc + 2][r] = va.z; As[lc + 3][r] = va.w;
            float4 vb = *(const float4*)(Wptr + (size_t)r * EMBED + k0 + lc);
            Bs[lc + 0][r] = vb.x; Bs[lc + 1][r] = vb.y;
            Bs[lc + 2][r] = vb.z; Bs[lc + 3][r] = vb.w;
        }
        __syncthreads();

#pragma unroll
        for (int k = 0; k < 16; k++) {
            float a[8], b[8];
            *(float4*)&a[0] = *(const float4*)&As[k][ty * 8];
            *(float4*)&a[4] = *(const float4*)&As[k][ty * 8 + 4];
            *(float4*)&b[0] = *(const float4*)&Bs[k][tx * 8];
            *(float4*)&b[4] = *(const float4*)&Bs[k][tx * 8 + 4];
#pragma unroll
            for (int i = 0; i < 8; i++)
#pragma unroll
                for (int j = 0; j < 8; j++)
                    acc[i][j] = fmaf(a[i], b[j], acc[i][j]);
        }
        __syncthreads();
    }

    if (NEPI == 0) {
        // scatter into Q/K/V [B,H,N,D]
#pragma unroll
        for (int i = 0; i < 8; i++) {
            int m  = m0 + ty * 8 + i;
            int b_ = m >> 11;          // / SEQ
            int nq = m & (SEQ - 1);
#pragma unroll
            for (int j = 0; j < 8; j++) {
                int n  = n0 + tx * 8 + j;
                float v = acc[i][j] + bias[n];
                int which = n >> 10;   // 0=q,1=k,2=v
                int e = n & 1023;
                int h = e >> 6;
                int d = e & 63;
                float* dst = (which == 0) ? g_q : (which == 1) ? g_k : g_v;
                dst[((((size_t)b_ * NHEADS) + h) * SEQ + nq) * HDIM + d] = v;
            }
        }
    } else {
#pragma unroll
        for (int i = 0; i < 8; i++) {
            int m = m0 + ty * 8 + i;
#pragma unroll
            for (int j = 0; j < 8; j++) {
                int n = n0 + tx * 8 + j;
                C[(size_t)m * EMBED + n] = acc[i][j] + bias[n];
            }
        }
    }
}

// ---------------------------------------------------------------------------
// Flash attention (fp32). grid = (SEQ/128, B*H). 256 threads.
// Per block: 128 query rows, D=64. Loops over 16 key tiles of 128.
// Smem: Qt[64][132] (transposed), Kt[64][132] (transposed),
//       Vs[128][64], Ps[128][128].  Total 165,888 B (dynamic).
// ---------------------------------------------------------------------------
#define QT_LEN (64 * 132)
#define VS_LEN (128 * 64)
#define PS_LEN (128 * 128)
#define ATTN_SMEM_BYTES ((2 * QT_LEN + VS_LEN + PS_LEN) * 4)

__global__ __launch_bounds__(256, 1) void attn_kernel()
{
    extern __shared__ float sm[];
    float* Qt = sm;                  // [64][132]  Qt[d][i]
    float* Kt = sm + QT_LEN;         // [64][132]  Kt[d][j]
    float* Vs = sm + 2 * QT_LEN;     // [128][64]  Vs[j][d]
    float* Ps = Vs + VS_LEN;         // [128][128] Ps[i][j]

    const int tid = threadIdx.x;
    const int ty  = tid >> 4;        // 0..15  (query-row group)
    const int tx  = tid & 15;        // 0..15
    const int bh  = blockIdx.y;      // b*NHEADS + h
    const int q0  = blockIdx.x * 128;

    const float* Qg = g_q + (size_t)bh * SEQ * HDIM;
    const float* Kg = g_k + (size_t)bh * SEQ * HDIM;
    const float* Vg = g_v + (size_t)bh * SEQ * HDIM;

    // Load Q tile, transposed: Qt[d][i]
    for (int idx = tid; idx < 128 * 16; idx += 256) {
        int r  = idx >> 4;
        int c4 = (idx & 15) << 2;
        float4 v = *(const float4*)(Qg + (size_t)(q0 + r) * HDIM + c4);
        Qt[(c4 + 0) * 132 + r] = v.x;
        Qt[(c4 + 1) * 132 + r] = v.y;
        Qt[(c4 + 2) * 132 + r] = v.z;
        Qt[(c4 + 3) * 132 + r] = v.w;
    }

    float m_r[8], l_r[8], o[8][4];
#pragma unroll
    for (int i = 0; i < 8; i++) {
        m_r[i] = -1e30f;
        l_r[i] = 0.f;
#pragma unroll
        for (int j = 0; j < 4; j++) o[i][j] = 0.f;
    }
    __syncthreads();

    for (int t = 0; t < SEQ / 128; t++) {
        const int k0 = t * 128;
        // Load K (transposed) and V (straight)
        for (int idx = tid; idx < 128 * 16; idx += 256) {
            int r  = idx >> 4;
            int c4 = (idx & 15) << 2;
            float4 kv = *(const float4*)(Kg + (size_t)(k0 + r) * HDIM + c4);
            Kt[(c4 + 0) * 132 + r] = kv.x;
            Kt[(c4 + 1) * 132 + r] = kv.y;
            Kt[(c4 + 2) * 132 + r] = kv.z;
            Kt[(c4 + 3) * 132 + r] = kv.w;
            float4 vv = *(const float4*)(Vg + (size_t)(k0 + r) * HDIM + c4);
            *(float4*)(Vs + r * 64 + c4) = vv;
        }
        __syncthreads();

        // S = (Q K^T) * 1/sqrt(D)
        float s[8][8];
#pragma unroll
        for (int i = 0; i < 8; i++)
#pragma unroll
            for (int j = 0; j < 8; j++) s[i][j] = 0.f;

#pragma unroll 8
        for (int d = 0; d < 64; d++) {
            float a[8], b[8];
            *(float4*)&a[0] = *(const float4*)&Qt[d * 132 + ty * 8];
            *(float4*)&a[4] = *(const float4*)&Qt[d * 132 + ty * 8 + 4];
            *(float4*)&b[0] = *(const float4*)&Kt[d * 132 + tx * 8];
            *(float4*)&b[4] = *(const float4*)&Kt[d * 132 + tx * 8 + 4];
#pragma unroll
            for (int i = 0; i < 8; i++)
#pragma unroll
                for (int j = 0; j < 8; j++)
                    s[i][j] = fmaf(a[i], b[j], s[i][j]);
        }

        // Online softmax update; write P to smem
        float corr[8];
#pragma unroll
        for (int r = 0; r < 8; r++) {
            float tmax = -1e30f;
#pragma unroll
            for (int c = 0; c < 8; c++) {
                s[r][c] *= 0.125f;   // 1/sqrt(64)
                tmax = fmaxf(tmax, s[r][c]);
            }
#pragma unroll
            for (int off = 8; off; off >>= 1)
                tmax = fmaxf(tmax, __shfl_xor_sync(0xffffffffu, tmax, off));
            float mnew = fmaxf(m_r[r], tmax);
            corr[r] = __expf(m_r[r] - mnew);
            m_r[r] = mnew;
            float rsum = 0.f;
#pragma unroll
            for (int c = 0; c < 8; c++) {
                float p = __expf(s[r][c] - mnew);
                s[r][c] = p;
                rsum += p;
            }
#pragma unroll
            for (int off = 8; off; off >>= 1)
                rsum += __shfl_xor_sync(0xffffffffu, rsum, off);
            l_r[r] = l_r[r] * corr[r] + rsum;
            *(float4*)&Ps[(ty * 8 + r) * 128 + tx * 8]     = *(float4*)&s[r][0];
            *(float4*)&Ps[(ty * 8 + r) * 128 + tx * 8 + 4] = *(float4*)&s[r][4];
        }
        __syncthreads();

        // O = O*corr + P @ V : thread owns rows ty*8..+7, cols tx*4..+3
#pragma unroll
        for (int r = 0; r < 8; r++)
#pragma unroll
            for (int c = 0; c < 4; c++) o[r][c] *= corr[r];

#pragma unroll 4
        for (int jj = 0; jj < 128; jj++) {
            float4 v = *(const float4*)&Vs[jj * 64 + tx * 4];
#pragma unroll
            for (int r = 0; r < 8; r++) {
                float p = Ps[(ty * 8 + r) * 128 + jj];
                o[r][0] = fmaf(p, v.x, o[r][0]);
                o[r][1] = fmaf(p, v.y, o[r][1]);
                o[r][2] = fmaf(p, v.z, o[r][2]);
                o[r][3] = fmaf(p, v.w, o[r][3]);
            }
        }
        __syncthreads();
    }

    // Finalize: divide by l, write attn output in [B,N,E] (E = h*64 + d)
    const int b_ = bh >> 4;
    const int h  = bh & 15;
#pragma unroll
    for (int r = 0; r < 8; r++) {
        float inv = 1.0f / l_r[r];
        int n = q0 + ty * 8 + r;
        float4 v = make_float4(o[r][0] * inv, o[r][1] * inv,
                               o[r][2] * inv, o[r][3] * inv);
        *(float4*)(g_attn + ((size_t)b_ * SEQ + n) * EMBED + h * 64 + tx * 4) = v;
    }
}

// ---------------------------------------------------------------------------
extern "C" void kernel_launch(void* const* d_in, const int* in_sizes, int n_in,
                              void* d_out, int out_size)
{
    (void)in_sizes; (void)n_in; (void)out_size;
    const float* x     = (const float*)d_in[0];
    const float* qkv_w = (const float*)d_in[1];
    const float* qkv_b = (const float*)d_in[2];
    const float* out_w = (const float*)d_in[3];
    const float* out_b = (const float*)d_in[4];
    float* out = (float*)d_out;

    cudaFuncSetAttribute(attn_kernel,
                         cudaFuncAttributeMaxDynamicSharedMemorySize,
                         ATTN_SMEM_BYTES);

    // 1) QKV projection + scatter to [B,H,N,D]
    gemm128<0><<<dim3(3 * EMBED / 128, MTOK / 128), 256>>>(x, qkv_w, qkv_b, nullptr);
    // 2) Flash attention per (b,h) / 128-query tile
    attn_kernel<<<dim3(SEQ / 128, BATCH * NHEADS), 256, ATTN_SMEM_BYTES>>>();
    // 3) Output projection
    gemm128<1><<<dim3(EMBED / 128, MTOK / 128), 256>>>(nullptr, out_w, out_b, out);
}

// round 9
// speedup vs baseline: 1.0720x; 1.0720x over previous
#include <cuda_runtime.h>
#include <cuda_bf16.h>
#include <mma.h>
#include <cstdint>

using namespace nvcuda;

// Problem constants
#define EMBED  1024
#define NHEADS 16
#define HDIM   64
#define BATCH  4
#define SEQ    2048
#define MTOK   (BATCH * SEQ)   // 8192

// ---------------------------------------------------------------------------
// Scratch — EXACTLY Round-1's globals (proven delta=0). Nothing else.
// ---------------------------------------------------------------------------
__device__ float g_q[BATCH * NHEADS * SEQ * HDIM];     // [B,H,N,D]
__device__ float g_k[BATCH * NHEADS * SEQ * HDIM];
__device__ float g_v[BATCH * NHEADS * SEQ * HDIM];
__device__ float g_attn[MTOK * EMBED];                 // [B,N,E]

// ---------------------------------------------------------------------------
// WMMA bf16x3 GEMM: C[m][n] = sum_k A[m][k]*W[n][k] + bias[n], K=1024.
// fp32 inputs are split to bf16 hi/lo IN-KERNEL (no split pass, no asm).
// Block tile 128x128, BK=32; 8 warps = (wm 0..3) x (wn 0..1), warp 32x64.
// Static smem: 4 x [128][32] bf16 (32KB) + patch 8x[16][20] f32 (10KB).
// EPI==0: QKV scatter to g_q/g_k/g_v.  EPI==1: A=g_attn, C=d_out.
// ---------------------------------------------------------------------------
template <int EPI>
__global__ __launch_bounds__(256) void gemm_wmma(
    const float* __restrict__ A, const float* __restrict__ W,
    const float* __restrict__ bias, float* __restrict__ C)
{
    __shared__ __align__(32) __nv_bfloat16 sAh[128][32];
    __shared__ __align__(32) __nv_bfloat16 sAl[128][32];
    __shared__ __align__(32) __nv_bfloat16 sBh[128][32];
    __shared__ __align__(32) __nv_bfloat16 sBl[128][32];
    __shared__ __align__(32) float sPatch[8][16][20];

    const int tid  = threadIdx.x;
    const int lane = tid & 31;
    const int w    = tid >> 5;
    const int wm   = w & 3;          // m slice of 32
    const int wn   = w >> 2;         // n slice of 64
    const int m0   = blockIdx.y * 128;
    const int n0   = blockIdx.x * 128;

    // loader mapping: 2 threads per row, each covers 16 contiguous k
    const int lrow = tid >> 1;
    const int lseg = (tid & 1) * 16;

    const float* Abase = (EPI == 1) ? (const float*)g_attn : A;
    const float* gA = Abase + (size_t)(m0 + lrow) * EMBED + lseg;
    const float* gW = W     + (size_t)(n0 + lrow) * EMBED + lseg;

    wmma::fragment<wmma::accumulator, 16, 16, 16, float> acc[2][4];
#pragma unroll
    for (int mt = 0; mt < 2; mt++)
#pragma unroll
        for (int nt = 0; nt < 4; nt++)
            wmma::fill_fragment(acc[mt][nt], 0.0f);

    for (int k0 = 0; k0 < EMBED; k0 += 32) {
        // load + split this k-block into smem
#pragma unroll
        for (int i = 0; i < 4; i++) {
            float4 va = *(const float4*)(gA + k0 + 4 * i);
            float4 vw = *(const float4*)(gW + k0 + 4 * i);
            const int c = lseg + 4 * i;
            __nv_bfloat16 h;
            h = __float2bfloat16_rn(va.x); sAh[lrow][c+0] = h;
            sAl[lrow][c+0] = __float2bfloat16_rn(va.x - __bfloat162float(h));
            h = __float2bfloat16_rn(va.y); sAh[lrow][c+1] = h;
            sAl[lrow][c+1] = __float2bfloat16_rn(va.y - __bfloat162float(h));
            h = __float2bfloat16_rn(va.z); sAh[lrow][c+2] = h;
            sAl[lrow][c+2] = __float2bfloat16_rn(va.z - __bfloat162float(h));
            h = __float2bfloat16_rn(va.w); sAh[lrow][c+3] = h;
            sAl[lrow][c+3] = __float2bfloat16_rn(va.w - __bfloat162float(h));
            h = __float2bfloat16_rn(vw.x); sBh[lrow][c+0] = h;
            sBl[lrow][c+0] = __float2bfloat16_rn(vw.x - __bfloat162float(h));
            h = __float2bfloat16_rn(vw.y); sBh[lrow][c+1] = h;
            sBl[lrow][c+1] = __float2bfloat16_rn(vw.y - __bfloat162float(h));
            h = __float2bfloat16_rn(vw.z); sBh[lrow][c+2] = h;
            sBl[lrow][c+2] = __float2bfloat16_rn(vw.z - __bfloat162float(h));
            h = __float2bfloat16_rn(vw.w); sBh[lrow][c+3] = h;
            sBl[lrow][c+3] = __float2bfloat16_rn(vw.w - __bfloat162float(h));
        }
        __syncthreads();

#pragma unroll
        for (int ks = 0; ks < 2; ks++) {
            const int kk = ks * 16;
            wmma::fragment<wmma::matrix_a, 16, 16, 16, __nv_bfloat16,
                           wmma::row_major> ah[2], al[2];
#pragma unroll
            for (int mt = 0; mt < 2; mt++) {
                wmma::load_matrix_sync(ah[mt], &sAh[wm * 32 + mt * 16][kk], 32);
                wmma::load_matrix_sync(al[mt], &sAl[wm * 32 + mt * 16][kk], 32);
            }
#pragma unroll
            for (int nt = 0; nt < 4; nt++) {
                // W stored [n][k] row-major == (k,n) col-major
                wmma::fragment<wmma::matrix_b, 16, 16, 16, __nv_bfloat16,
                               wmma::col_major> bh, bl;
                wmma::load_matrix_sync(bh, &sBh[wn * 64 + nt * 16][kk], 32);
                wmma::load_matrix_sync(bl, &sBl[wn * 64 + nt * 16][kk], 32);
#pragma unroll
                for (int mt = 0; mt < 2; mt++) {
                    wmma::mma_sync(acc[mt][nt], ah[mt], bh, acc[mt][nt]);
                    wmma::mma_sync(acc[mt][nt], ah[mt], bl, acc[mt][nt]);
                    wmma::mma_sync(acc[mt][nt], al[mt], bh, acc[mt][nt]);
                }
            }
        }
        __syncthreads();
    }

    // Epilogue: per-warp patch -> bias add -> scatter
    float* patch = &sPatch[w][0][0];
    const int pr = lane >> 1;
    const int pc = (lane & 1) * 8;
#pragma unroll
    for (int mt = 0; mt < 2; mt++)
#pragma unroll
        for (int nt = 0; nt < 4; nt++) {
            wmma::store_matrix_sync(patch, acc[mt][nt], 20, wmma::mem_row_major);
            __syncwarp();
            const int m = m0 + wm * 32 + mt * 16 + pr;
            const int n = n0 + wn * 64 + nt * 16 + pc;
            float4 p0 = *(const float4*)&patch[pr * 20 + pc];
            float4 p1 = *(const float4*)&patch[pr * 20 + pc + 4];
            float4 b0 = *(const float4*)&bias[n];
            float4 b1 = *(const float4*)&bias[n + 4];
            p0.x += b0.x; p0.y += b0.y; p0.z += b0.z; p0.w += b0.w;
            p1.x += b1.x; p1.y += b1.y; p1.z += b1.z; p1.w += b1.w;
            if (EPI == 0) {
                const int b_ = m >> 11, nq = m & (SEQ - 1);
                const int which = n >> 10, e = n & 1023;
                const int h = e >> 6, d = e & 63;
                float* dst = (which == 0) ? g_q : (which == 1) ? g_k : g_v;
                float* p = dst + ((((size_t)b_ * NHEADS) + h) * SEQ + nq) * HDIM + d;
                *(float4*)(p)     = p0;
                *(float4*)(p + 4) = p1;
            } else {
                float* p = C + (size_t)m * EMBED + n;
                *(float4*)(p)     = p0;
                *(float4*)(p + 4) = p1;
            }
            __syncwarp();
        }
}

// ---------------------------------------------------------------------------
// Flash attention — byte-exact Round-1 kernel (proven delta=0).
// ---------------------------------------------------------------------------
#define QT_LEN (64 * 132)
#define VS_LEN (128 * 64)
#define PS_LEN (128 * 128)
#define ATTN_SMEM_BYTES ((2 * QT_LEN + VS_LEN + PS_LEN) * 4)

__global__ __launch_bounds__(256, 1) void attn_kernel()
{
    extern __shared__ float sm[];
    float* Qt = sm;                  // [64][132]  Qt[d][i]
    float* Kt = sm + QT_LEN;         // [64][132]  Kt[d][j]
    float* Vs = sm + 2 * QT_LEN;     // [128][64]
    float* Ps = Vs + VS_LEN;         // [128][128]

    const int tid = threadIdx.x;
    const int ty  = tid >> 4;
    const int tx  = tid & 15;
    const int bh  = blockIdx.y;
    const int q0  = blockIdx.x * 128;

    const float* Qg = g_q + (size_t)bh * SEQ * HDIM;
    const float* Kg = g_k + (size_t)bh * SEQ * HDIM;
    const float* Vg = g_v + (size_t)bh * SEQ * HDIM;

    for (int idx = tid; idx < 128 * 16; idx += 256) {
        int r  = idx >> 4;
        int c4 = (idx & 15) << 2;
        float4 v = *(const float4*)(Qg + (size_t)(q0 + r) * HDIM + c4);
        Qt[(c4 + 0) * 132 + r] = v.x;
        Qt[(c4 + 1) * 132 + r] = v.y;
        Qt[(c4 + 2) * 132 + r] = v.z;
        Qt[(c4 + 3) * 132 + r] = v.w;
    }

    float m_r[8], l_r[8], o[8][4];
#pragma unroll
    for (int i = 0; i < 8; i++) {
        m_r[i] = -1e30f;
        l_r[i] = 0.f;
#pragma unroll
        for (int j = 0; j < 4; j++) o[i][j] = 0.f;
    }
    __syncthreads();

    for (int t = 0; t < SEQ / 128; t++) {
        const int k0 = t * 128;
        for (int idx = tid; idx < 128 * 16; idx += 256) {
            int r  = idx >> 4;
            int c4 = (idx & 15) << 2;
            float4 kv = *(const float4*)(Kg + (size_t)(k0 + r) * HDIM + c4);
            Kt[(c4 + 0) * 132 + r] = kv.x;
            Kt[(c4 + 1) * 132 + r] = kv.y;
            Kt[(c4 + 2) * 132 + r] = kv.z;
            Kt[(c4 + 3) * 132 + r] = kv.w;
            float4 vv = *(const float4*)(Vg + (size_t)(k0 + r) * HDIM + c4);
            *(float4*)(Vs + r * 64 + c4) = vv;
        }
        __syncthreads();

        float s[8][8];
#pragma unroll
        for (int i = 0; i < 8; i++)
#pragma unroll
            for (int j = 0; j < 8; j++) s[i][j] = 0.f;

#pragma unroll 8
        for (int d = 0; d < 64; d++) {
            float a[8], b[8];
            *(float4*)&a[0] = *(const float4*)&Qt[d * 132 + ty * 8];
            *(float4*)&a[4] = *(const float4*)&Qt[d * 132 + ty * 8 + 4];
            *(float4*)&b[0] = *(const float4*)&Kt[d * 132 + tx * 8];
            *(float4*)&b[4] = *(const float4*)&Kt[d * 132 + tx * 8 + 4];
#pragma unroll
            for (int i = 0; i < 8; i++)
#pragma unroll
                for (int j = 0; j < 8; j++)
                    s[i][j] = fmaf(a[i], b[j], s[i][j]);
        }

        float corr[8];
#pragma unroll
        for (int r = 0; r < 8; r++) {
            float tmax = -1e30f;
#pragma unroll
            for (int c = 0; c < 8; c++) {
                s[r][c] *= 0.125f;
                tmax = fmaxf(tmax, s[r][c]);
            }
#pragma unroll
            for (int off = 8; off; off >>= 1)
                tmax = fmaxf(tmax, __shfl_xor_sync(0xffffffffu, tmax, off));
            float mnew = fmaxf(m_r[r], tmax);
            corr[r] = __expf(m_r[r] - mnew);
            m_r[r] = mnew;
            float rsum = 0.f;
#pragma unroll
            for (int c = 0; c < 8; c++) {
                float p = __expf(s[r][c] - mnew);
                s[r][c] = p;
                rsum += p;
            }
#pragma unroll
            for (int off = 8; off; off >>= 1)
                rsum += __shfl_xor_sync(0xffffffffu, rsum, off);
            l_r[r] = l_r[r] * corr[r] + rsum;
            *(float4*)&Ps[(ty * 8 + r) * 128 + tx * 8]     = *(float4*)&s[r][0];
            *(float4*)&Ps[(ty * 8 + r) * 128 + tx * 8 + 4] = *(float4*)&s[r][4];
        }
        __syncthreads();

#pragma unroll
        for (int r = 0; r < 8; r++)
#pragma unroll
            for (int c = 0; c < 4; c++) o[r][c] *= corr[r];

#pragma unroll 4
        for (int jj = 0; jj < 128; jj++) {
            float4 v = *(const float4*)&Vs[jj * 64 + tx * 4];
#pragma unroll
            for (int r = 0; r < 8; r++) {
                float p = Ps[(ty * 8 + r) * 128 + jj];
                o[r][0] = fmaf(p, v.x, o[r][0]);
                o[r][1] = fmaf(p, v.y, o[r][1]);
                o[r][2] = fmaf(p, v.z, o[r][2]);
                o[r][3] = fmaf(p, v.w, o[r][3]);
            }
        }
        __syncthreads();
    }

    const int b_ = bh >> 4;
    const int h  = bh & 15;
#pragma unroll
    for (int r = 0; r < 8; r++) {
        float inv = 1.0f / l_r[r];
        int n = q0 + ty * 8 + r;
        float4 v = make_float4(o[r][0] * inv, o[r][1] * inv,
                               o[r][2] * inv, o[r][3] * inv);
        *(float4*)(g_attn + ((size_t)b_ * SEQ + n) * EMBED + h * 64 + tx * 4) = v;
    }
}

// ---------------------------------------------------------------------------
extern "C" void kernel_launch(void* const* d_in, const int* in_sizes, int n_in,
                              void* d_out, int out_size)
{
    (void)in_sizes; (void)n_in; (void)out_size;
    const float* x     = (const float*)d_in[0];
    const float* qkv_w = (const float*)d_in[1];
    const float* qkv_b = (const float*)d_in[2];
    const float* out_w = (const float*)d_in[3];
    const float* out_b = (const float*)d_in[4];
    float* out = (float*)d_out;

    cudaFuncSetAttribute(attn_kernel,
                         cudaFuncAttributeMaxDynamicSharedMemorySize,
                         ATTN_SMEM_BYTES);

    // 1) QKV projection (WMMA bf16x3) + scatter to [B,H,N,D]
    gemm_wmma<0><<<dim3(3 * EMBED / 128, MTOK / 128), 256>>>(
        x, qkv_w, qkv_b, nullptr);
    // 2) Flash attention (exact R1 kernel) -> g_attn fp32
    attn_kernel<<<dim3(SEQ / 128, BATCH * NHEADS), 256, ATTN_SMEM_BYTES>>>();
    // 3) Output projection (WMMA bf16x3)
    gemm_wmma<1><<<dim3(EMBED / 128, MTOK / 128), 256>>>(
        nullptr, out_w, out_b, out);
}

// round 10
// speedup vs baseline: 1.3586x; 1.2674x over previous
#include <cuda_runtime.h>
#include <cuda_bf16.h>
#include <mma.h>
#include <cstdint>

using namespace nvcuda;

// Problem constants
#define EMBED  1024
#define NHEADS 16
#define HDIM   64
#define BATCH  4
#define SEQ    2048
#define MTOK   (BATCH * SEQ)   // 8192

// ---------------------------------------------------------------------------
// Scratch — same four globals as R1/R9 (proven delta=0).
// ---------------------------------------------------------------------------
__device__ float g_q[BATCH * NHEADS * SEQ * HDIM];     // [B,H,N,D]
__device__ float g_k[BATCH * NHEADS * SEQ * HDIM];
__device__ float g_v[BATCH * NHEADS * SEQ * HDIM];
__device__ float g_attn[MTOK * EMBED];                 // [B,N,E]

__device__ __forceinline__ void sp_bf16(float x, __nv_bfloat16& h, __nv_bfloat16& l)
{
    h = __float2bfloat16_rn(x);
    l = __float2bfloat16_rn(x - __bfloat162float(h));
}

// ---------------------------------------------------------------------------
// WMMA bf16x3 GEMM — byte-identical to Round 9 (passing).
// ---------------------------------------------------------------------------
template <int EPI>
__global__ __launch_bounds__(256) void gemm_wmma(
    const float* __restrict__ A, const float* __restrict__ W,
    const float* __restrict__ bias, float* __restrict__ C)
{
    __shared__ __align__(32) __nv_bfloat16 sAh[128][32];
    __shared__ __align__(32) __nv_bfloat16 sAl[128][32];
    __shared__ __align__(32) __nv_bfloat16 sBh[128][32];
    __shared__ __align__(32) __nv_bfloat16 sBl[128][32];
    __shared__ __align__(32) float sPatch[8][16][20];

    const int tid  = threadIdx.x;
    const int lane = tid & 31;
    const int w    = tid >> 5;
    const int wm   = w & 3;
    const int wn   = w >> 2;
    const int m0   = blockIdx.y * 128;
    const int n0   = blockIdx.x * 128;

    const int lrow = tid >> 1;
    const int lseg = (tid & 1) * 16;

    const float* Abase = (EPI == 1) ? (const float*)g_attn : A;
    const float* gA = Abase + (size_t)(m0 + lrow) * EMBED + lseg;
    const float* gW = W     + (size_t)(n0 + lrow) * EMBED + lseg;

    wmma::fragment<wmma::accumulator, 16, 16, 16, float> acc[2][4];
#pragma unroll
    for (int mt = 0; mt < 2; mt++)
#pragma unroll
        for (int nt = 0; nt < 4; nt++)
            wmma::fill_fragment(acc[mt][nt], 0.0f);

    for (int k0 = 0; k0 < EMBED; k0 += 32) {
#pragma unroll
        for (int i = 0; i < 4; i++) {
            float4 va = *(const float4*)(gA + k0 + 4 * i);
            float4 vw = *(const float4*)(gW + k0 + 4 * i);
            const int c = lseg + 4 * i;
            __nv_bfloat16 h, l;
            sp_bf16(va.x, h, l); sAh[lrow][c+0] = h; sAl[lrow][c+0] = l;
            sp_bf16(va.y, h, l); sAh[lrow][c+1] = h; sAl[lrow][c+1] = l;
            sp_bf16(va.z, h, l); sAh[lrow][c+2] = h; sAl[lrow][c+2] = l;
            sp_bf16(va.w, h, l); sAh[lrow][c+3] = h; sAl[lrow][c+3] = l;
            sp_bf16(vw.x, h, l); sBh[lrow][c+0] = h; sBl[lrow][c+0] = l;
            sp_bf16(vw.y, h, l); sBh[lrow][c+1] = h; sBl[lrow][c+1] = l;
            sp_bf16(vw.z, h, l); sBh[lrow][c+2] = h; sBl[lrow][c+2] = l;
            sp_bf16(vw.w, h, l); sBh[lrow][c+3] = h; sBl[lrow][c+3] = l;
        }
        __syncthreads();

#pragma unroll
        for (int ks = 0; ks < 2; ks++) {
            const int kk = ks * 16;
            wmma::fragment<wmma::matrix_a, 16, 16, 16, __nv_bfloat16,
                           wmma::row_major> ah[2], al[2];
#pragma unroll
            for (int mt = 0; mt < 2; mt++) {
                wmma::load_matrix_sync(ah[mt], &sAh[wm * 32 + mt * 16][kk], 32);
                wmma::load_matrix_sync(al[mt], &sAl[wm * 32 + mt * 16][kk], 32);
            }
#pragma unroll
            for (int nt = 0; nt < 4; nt++) {
                wmma::fragment<wmma::matrix_b, 16, 16, 16, __nv_bfloat16,
                               wmma::col_major> bh, bl;
                wmma::load_matrix_sync(bh, &sBh[wn * 64 + nt * 16][kk], 32);
                wmma::load_matrix_sync(bl, &sBl[wn * 64 + nt * 16][kk], 32);
#pragma unroll
                for (int mt = 0; mt < 2; mt++) {
                    wmma::mma_sync(acc[mt][nt], ah[mt], bh, acc[mt][nt]);
                    wmma::mma_sync(acc[mt][nt], ah[mt], bl, acc[mt][nt]);
                    wmma::mma_sync(acc[mt][nt], al[mt], bh, acc[mt][nt]);
                }
            }
        }
        __syncthreads();
    }

    float* patch = &sPatch[w][0][0];
    const int pr = lane >> 1;
    const int pc = (lane & 1) * 8;
#pragma unroll
    for (int mt = 0; mt < 2; mt++)
#pragma unroll
        for (int nt = 0; nt < 4; nt++) {
            wmma::store_matrix_sync(patch, acc[mt][nt], 20, wmma::mem_row_major);
            __syncwarp();
            const int m = m0 + wm * 32 + mt * 16 + pr;
            const int n = n0 + wn * 64 + nt * 16 + pc;
            float4 p0 = *(const float4*)&patch[pr * 20 + pc];
            float4 p1 = *(const float4*)&patch[pr * 20 + pc + 4];
            float4 b0 = *(const float4*)&bias[n];
            float4 b1 = *(const float4*)&bias[n + 4];
            p0.x += b0.x; p0.y += b0.y; p0.z += b0.z; p0.w += b0.w;
            p1.x += b1.x; p1.y += b1.y; p1.z += b1.z; p1.w += b1.w;
            if (EPI == 0) {
                const int b_ = m >> 11, nq = m & (SEQ - 1);
                const int which = n >> 10, e = n & 1023;
                const int h = e >> 6, d = e & 63;
                float* dst = (which == 0) ? g_q : (which == 1) ? g_k : g_v;
                float* p = dst + ((((size_t)b_ * NHEADS) + h) * SEQ + nq) * HDIM + d;
                *(float4*)(p)     = p0;
                *(float4*)(p + 4) = p1;
            } else {
                float* p = C + (size_t)m * EMBED + n;
                *(float4*)(p)     = p0;
                *(float4*)(p + 4) = p1;
            }
            __syncwarp();
        }
}

// ---------------------------------------------------------------------------
// WMMA flash attention. Per block: 128 q-rows, one (b,h). 256 threads.
// S = QK^T and O += P V on tensor cores (bf16 hi/lo 3-term split);
// softmax scalar fp32 (R1 logic). Dynamic smem 215,040 B.
// ---------------------------------------------------------------------------
#define OFF_QH 0
#define OFF_QL 18432
#define OFF_KH 36864
#define OFF_KL 55296
#define OFF_VH 73728
#define OFF_VL 92160
#define OFF_S  110592            // f32 [128][136]; overlaid by Ph/Pl after softmax
#define OFF_PH 110592            // bf16 [128][136]
#define OFF_PL 145408            // bf16 [128][136]
#define OFF_OS 180224            // f32 [128][68]
#define ATTN_SMEM_BYTES 215040

__global__ __launch_bounds__(256, 1) void attn_wmma()
{
    extern __shared__ char smc[];
    __nv_bfloat16* Qh = (__nv_bfloat16*)(smc + OFF_QH);   // [128][72]
    __nv_bfloat16* Ql = (__nv_bfloat16*)(smc + OFF_QL);
    __nv_bfloat16* Kh = (__nv_bfloat16*)(smc + OFF_KH);
    __nv_bfloat16* Kl = (__nv_bfloat16*)(smc + OFF_KL);
    __nv_bfloat16* Vh = (__nv_bfloat16*)(smc + OFF_VH);
    __nv_bfloat16* Vl = (__nv_bfloat16*)(smc + OFF_VL);
    float*         S  = (float*)        (smc + OFF_S);    // [128][136]
    __nv_bfloat16* Ph = (__nv_bfloat16*)(smc + OFF_PH);
    __nv_bfloat16* Pl = (__nv_bfloat16*)(smc + OFF_PL);
    float*         Os = (float*)        (smc + OFF_OS);   // [128][68]

    const int tid  = threadIdx.x;
    const int lane = tid & 31;
    const int w    = tid >> 5;
    const int wm   = w & 3;          // 32-row slice
    const int wn   = w >> 2;         // 0..1
    const int ty   = tid >> 4;       // softmax row group
    const int tx   = tid & 15;
    const int bh   = blockIdx.y;
    const int q0   = blockIdx.x * 128;
    (void)lane;

    const float* Qg = g_q + (size_t)bh * SEQ * HDIM;
    const float* Kg = g_k + (size_t)bh * SEQ * HDIM;
    const float* Vg = g_v + (size_t)bh * SEQ * HDIM;

    // Load + split Q tile: 2048 float4 chunks, 8 per thread
#pragma unroll
    for (int i = 0; i < 8; i++) {
        int idx = tid + i * 256;
        int r   = idx >> 4;
        int c4  = (idx & 15) * 4;
        float4 v = *(const float4*)(Qg + (size_t)(q0 + r) * HDIM + c4);
        __nv_bfloat16 h, l;
        sp_bf16(v.x, h, l); Qh[r * 72 + c4 + 0] = h; Ql[r * 72 + c4 + 0] = l;
        sp_bf16(v.y, h, l); Qh[r * 72 + c4 + 1] = h; Ql[r * 72 + c4 + 1] = l;
        sp_bf16(v.z, h, l); Qh[r * 72 + c4 + 2] = h; Ql[r * 72 + c4 + 2] = l;
        sp_bf16(v.w, h, l); Qh[r * 72 + c4 + 3] = h; Ql[r * 72 + c4 + 3] = l;
    }

    float m_r[8], l_r[8], corr[8], o[8][4];
#pragma unroll
    for (int i = 0; i < 8; i++) {
        m_r[i] = -1e30f;
        l_r[i] = 0.f;
#pragma unroll
        for (int j = 0; j < 4; j++) o[i][j] = 0.f;
    }
    __syncthreads();

    for (int t = 0; t < SEQ / 128; t++) {
        const int k0 = t * 128;
        // Load + split K and V tiles
#pragma unroll
        for (int i = 0; i < 8; i++) {
            int idx = tid + i * 256;
            int r   = idx >> 4;
            int c4  = (idx & 15) * 4;
            float4 kv = *(const float4*)(Kg + (size_t)(k0 + r) * HDIM + c4);
            __nv_bfloat16 h, l;
            sp_bf16(kv.x, h, l); Kh[r * 72 + c4 + 0] = h; Kl[r * 72 + c4 + 0] = l;
            sp_bf16(kv.y, h, l); Kh[r * 72 + c4 + 1] = h; Kl[r * 72 + c4 + 1] = l;
            sp_bf16(kv.z, h, l); Kh[r * 72 + c4 + 2] = h; Kl[r * 72 + c4 + 2] = l;
            sp_bf16(kv.w, h, l); Kh[r * 72 + c4 + 3] = h; Kl[r * 72 + c4 + 3] = l;
            float4 vv = *(const float4*)(Vg + (size_t)(k0 + r) * HDIM + c4);
            sp_bf16(vv.x, h, l); Vh[r * 72 + c4 + 0] = h; Vl[r * 72 + c4 + 0] = l;
            sp_bf16(vv.y, h, l); Vh[r * 72 + c4 + 1] = h; Vl[r * 72 + c4 + 1] = l;
            sp_bf16(vv.z, h, l); Vh[r * 72 + c4 + 2] = h; Vl[r * 72 + c4 + 2] = l;
            sp_bf16(vv.w, h, l); Vh[r * 72 + c4 + 3] = h; Vl[r * 72 + c4 + 3] = l;
        }
        __syncthreads();

        // ---- S = Q K^T (warp 32x64 tile), bf16x3 ----
        {
            wmma::fragment<wmma::accumulator, 16, 16, 16, float> accS[2][4];
#pragma unroll
            for (int mt = 0; mt < 2; mt++)
#pragma unroll
                for (int nt = 0; nt < 4; nt++)
                    wmma::fill_fragment(accS[mt][nt], 0.0f);

#pragma unroll
            for (int kk = 0; kk < 4; kk++) {
                const int k = kk * 16;
                wmma::fragment<wmma::matrix_a, 16, 16, 16, __nv_bfloat16,
                               wmma::row_major> ah[2], al[2];
#pragma unroll
                for (int mt = 0; mt < 2; mt++) {
                    wmma::load_matrix_sync(ah[mt], &Qh[(wm * 32 + mt * 16) * 72 + k], 72);
                    wmma::load_matrix_sync(al[mt], &Ql[(wm * 32 + mt * 16) * 72 + k], 72);
                }
#pragma unroll
                for (int nt = 0; nt < 4; nt++) {
                    wmma::fragment<wmma::matrix_b, 16, 16, 16, __nv_bfloat16,
                                   wmma::col_major> bh, bl;
                    wmma::load_matrix_sync(bh, &Kh[(wn * 64 + nt * 16) * 72 + k], 72);
                    wmma::load_matrix_sync(bl, &Kl[(wn * 64 + nt * 16) * 72 + k], 72);
#pragma unroll
                    for (int mt = 0; mt < 2; mt++) {
                        wmma::mma_sync(accS[mt][nt], ah[mt], bh, accS[mt][nt]);
                        wmma::mma_sync(accS[mt][nt], ah[mt], bl, accS[mt][nt]);
                        wmma::mma_sync(accS[mt][nt], al[mt], bh, accS[mt][nt]);
                    }
                }
            }
#pragma unroll
            for (int mt = 0; mt < 2; mt++)
#pragma unroll
                for (int nt = 0; nt < 4; nt++)
                    wmma::store_matrix_sync(
                        &S[(wm * 32 + mt * 16) * 136 + wn * 64 + nt * 16],
                        accS[mt][nt], 136, wmma::mem_row_major);
        }
        __syncthreads();

        // ---- scalar online softmax (R1 logic); p kept in regs ----
        float s[8][8];
#pragma unroll
        for (int r = 0; r < 8; r++) {
            *(float4*)&s[r][0] = *(const float4*)&S[(ty * 8 + r) * 136 + tx * 8];
            *(float4*)&s[r][4] = *(const float4*)&S[(ty * 8 + r) * 136 + tx * 8 + 4];
        }
#pragma unroll
        for (int r = 0; r < 8; r++) {
            float tmax = -1e30f;
#pragma unroll
            for (int c = 0; c < 8; c++) {
                s[r][c] *= 0.125f;
                tmax = fmaxf(tmax, s[r][c]);
            }
#pragma unroll
            for (int off = 8; off; off >>= 1)
                tmax = fmaxf(tmax, __shfl_xor_sync(0xffffffffu, tmax, off));
            float mnew = fmaxf(m_r[r], tmax);
            corr[r] = __expf(m_r[r] - mnew);
            m_r[r] = mnew;
            float rsum = 0.f;
#pragma unroll
            for (int c = 0; c < 8; c++) {
                float p = __expf(s[r][c] - mnew);
                s[r][c] = p;
                rsum += p;
            }
#pragma unroll
            for (int off = 8; off; off >>= 1)
                rsum += __shfl_xor_sync(0xffffffffu, rsum, off);
            l_r[r] = l_r[r] * corr[r] + rsum;
        }
        __syncthreads();   // all S reads done before Ph/Pl overlay writes

#pragma unroll
        for (int r = 0; r < 8; r++)
#pragma unroll
            for (int c = 0; c < 8; c++) {
                __nv_bfloat16 h, l;
                sp_bf16(s[r][c], h, l);
                Ph[(ty * 8 + r) * 136 + tx * 8 + c] = h;
                Pl[(ty * 8 + r) * 136 + tx * 8 + c] = l;
            }
        __syncthreads();

        // ---- O_tile = P V (warp 32x32 tile), bf16x3 ----
        {
            wmma::fragment<wmma::accumulator, 16, 16, 16, float> accO[2][2];
#pragma unroll
            for (int mt = 0; mt < 2; mt++)
#pragma unroll
                for (int nt = 0; nt < 2; nt++)
                    wmma::fill_fragment(accO[mt][nt], 0.0f);

#pragma unroll
            for (int kk = 0; kk < 8; kk++) {
                const int k = kk * 16;
                wmma::fragment<wmma::matrix_a, 16, 16, 16, __nv_bfloat16,
                               wmma::row_major> ph[2], pl[2];
#pragma unroll
                for (int mt = 0; mt < 2; mt++) {
                    wmma::load_matrix_sync(ph[mt], &Ph[(wm * 32 + mt * 16) * 136 + k], 136);
                    wmma::load_matrix_sync(pl[mt], &Pl[(wm * 32 + mt * 16) * 136 + k], 136);
                }
#pragma unroll
                for (int nt = 0; nt < 2; nt++) {
                    wmma::fragment<wmma::matrix_b, 16, 16, 16, __nv_bfloat16,
                                   wmma::row_major> vbh, vbl;
                    wmma::load_matrix_sync(vbh, &Vh[k * 72 + wn * 32 + nt * 16], 72);
                    wmma::load_matrix_sync(vbl, &Vl[k * 72 + wn * 32 + nt * 16], 72);
#pragma unroll
                    for (int mt = 0; mt < 2; mt++) {
                        wmma::mma_sync(accO[mt][nt], ph[mt], vbh, accO[mt][nt]);
                        wmma::mma_sync(accO[mt][nt], ph[mt], vbl, accO[mt][nt]);
                        wmma::mma_sync(accO[mt][nt], pl[mt], vbh, accO[mt][nt]);
                    }
                }
            }
#pragma unroll
            for (int mt = 0; mt < 2; mt++)
#pragma unroll
                for (int nt = 0; nt < 2; nt++)
                    wmma::store_matrix_sync(
                        &Os[(wm * 32 + mt * 16) * 68 + wn * 32 + nt * 16],
                        accO[mt][nt], 68, wmma::mem_row_major);
        }
        __syncthreads();

        // ---- scalar O accumulate with rescale ----
#pragma unroll
        for (int r = 0; r < 8; r++) {
            float4 pv = *(const float4*)&Os[(ty * 8 + r) * 68 + tx * 4];
            o[r][0] = o[r][0] * corr[r] + pv.x;
            o[r][1] = o[r][1] * corr[r] + pv.y;
            o[r][2] = o[r][2] * corr[r] + pv.z;
            o[r][3] = o[r][3] * corr[r] + pv.w;
        }
        __syncthreads();   // before next tile overwrites K/V/S
    }

    // Finalize -> g_attn [B,N,E]
    const int b_ = bh >> 4;
    const int h  = bh & 15;
#pragma unroll
    for (int r = 0; r < 8; r++) {
        float inv = 1.0f / l_r[r];
        int n = q0 + ty * 8 + r;
        float4 v = make_float4(o[r][0] * inv, o[r][1] * inv,
                               o[r][2] * inv, o[r][3] * inv);
        *(float4*)(g_attn + ((size_t)b_ * SEQ + n) * EMBED + h * 64 + tx * 4) = v;
    }
}

// ---------------------------------------------------------------------------
extern "C" void kernel_launch(void* const* d_in, const int* in_sizes, int n_in,
                              void* d_out, int out_size)
{
    (void)in_sizes; (void)n_in; (void)out_size;
    const float* x     = (const float*)d_in[0];
    const float* qkv_w = (const float*)d_in[1];
    const float* qkv_b = (const float*)d_in[2];
    const float* out_w = (const float*)d_in[3];
    const float* out_b = (const float*)d_in[4];
    float* out = (float*)d_out;

    cudaFuncSetAttribute(attn_wmma,
                         cudaFuncAttributeMaxDynamicSharedMemorySize,
                         ATTN_SMEM_BYTES);

    // 1) QKV projection (WMMA bf16x3) + scatter to [B,H,N,D]
    gemm_wmma<0><<<dim3(3 * EMBED / 128, MTOK / 128), 256>>>(
        x, qkv_w, qkv_b, nullptr);
    // 2) Flash attention (WMMA bf16x3 + fp32 softmax) -> g_attn
    attn_wmma<<<dim3(SEQ / 128, BATCH * NHEADS), 256, ATTN_SMEM_BYTES>>>();
    // 3) Output projection (WMMA bf16x3)
    gemm_wmma<1><<<dim3(EMBED / 128, MTOK / 128), 256>>>(
        nullptr, out_w, out_b, out);
}

// round 12
// speedup vs baseline: 1.6657x; 1.2260x over previous
#include <cuda_runtime.h>
#include <cuda_bf16.h>
#include <mma.h>
#include <cstdint>

using namespace nvcuda;

// Problem constants
#define EMBED  1024
#define NHEADS 16
#define HDIM   64
#define BATCH  4
#define SEQ    2048
#define MTOK   (BATCH * SEQ)   // 8192

// ---------------------------------------------------------------------------
// Scratch — EXACTLY the proven-safe 128 MB footprint (R1/R9/R10). No more.
// ---------------------------------------------------------------------------
__device__ float g_q[BATCH * NHEADS * SEQ * HDIM];     // [B,H,N,D]
__device__ float g_k[BATCH * NHEADS * SEQ * HDIM];
__device__ float g_v[BATCH * NHEADS * SEQ * HDIM];
__device__ float g_attn[MTOK * EMBED];                 // [B,N,E]

__device__ __forceinline__ void sp_bf16(float x, __nv_bfloat16& h, __nv_bfloat16& l)
{
    h = __float2bfloat16_rn(x);
    l = __float2bfloat16_rn(x - __bfloat162float(h));
}

// split a float4 and store 4 hi + 4 lo bf16 at H/L + off (off 2-elem aligned)
__device__ __forceinline__ void st_split4(
    __nv_bfloat16* H, __nv_bfloat16* L, int off, float4 v)
{
    __nv_bfloat16 hx, lx, hy, ly, hz, lz, hw, lw;
    sp_bf16(v.x, hx, lx); sp_bf16(v.y, hy, ly);
    sp_bf16(v.z, hz, lz); sp_bf16(v.w, hw, lw);
    *(__nv_bfloat162*)(H + off)     = __nv_bfloat162(hx, hy);
    *(__nv_bfloat162*)(H + off + 2) = __nv_bfloat162(hz, hw);
    *(__nv_bfloat162*)(L + off)     = __nv_bfloat162(lx, ly);
    *(__nv_bfloat162*)(L + off + 2) = __nv_bfloat162(lz, lw);
}

// ---------------------------------------------------------------------------
// WMMA bf16x3 GEMM with register prefetch + smem double buffer.
// C[m][n] = sum_k A[m][k]*W[n][k] + bias[n], K=1024, fp32 inputs split
// in-kernel on the smem store path (no extra globals, no split pass).
// Block 128x128, BK=32, 8 warps (wm 0..3 x wn 0..1) each 32x64.
// Dynamic smem: 2 x 4 x [128][40] bf16 = 81920 B + patch 10240 B = 92160 B.
// ---------------------------------------------------------------------------
#define LDSG  40
#define MATG  (128 * LDSG)                 // elems per matrix tile
#define BUFG  (4 * MATG)                   // elems per buffer (Ah|Al|Bh|Bl)
#define GEMM_SMEM (2 * BUFG * 2 + 8 * 16 * 20 * 4)   // 92160 B
#define NKBG  (EMBED / 32)                 // 32

template <int EPI>
__global__ __launch_bounds__(256) void gemm_wmma(
    const float* __restrict__ A, const float* __restrict__ W,
    const float* __restrict__ bias, float* __restrict__ C)
{
    extern __shared__ __align__(16) char dsm[];
    __nv_bfloat16* sm0 = (__nv_bfloat16*)dsm;           // [2][4][128][40]
    float* sPatchAll   = (float*)(dsm + 2 * BUFG * 2);  // [8][16][20]

    const int tid  = threadIdx.x;
    const int lane = tid & 31;
    const int w    = tid >> 5;
    const int wm   = w & 3;
    const int wn   = w >> 2;
    const int m0   = blockIdx.y * 128;
    const int n0   = blockIdx.x * 128;

    // loader: 2 threads per row, each covers 16 contiguous k (4 float4)
    const int lrow = tid >> 1;
    const int lseg = (tid & 1) * 16;

    const float* Abase = (EPI == 1) ? (const float*)g_attn : A;
    const float* gA = Abase + (size_t)(m0 + lrow) * EMBED + lseg;
    const float* gW = W     + (size_t)(n0 + lrow) * EMBED + lseg;

    wmma::fragment<wmma::accumulator, 16, 16, 16, float> acc[2][4];
#pragma unroll
    for (int mt = 0; mt < 2; mt++)
#pragma unroll
        for (int nt = 0; nt < 4; nt++)
            wmma::fill_fragment(acc[mt][nt], 0.0f);

    float4 pa[4], pw[4];

    // prologue: k-block 0 -> regs -> buffer 0
#pragma unroll
    for (int j = 0; j < 4; j++) {
        pa[j] = *(const float4*)(gA + 4 * j);
        pw[j] = *(const float4*)(gW + 4 * j);
    }
    {
        __nv_bfloat16* bAh = sm0;
        __nv_bfloat16* bAl = sm0 + MATG;
        __nv_bfloat16* bBh = sm0 + 2 * MATG;
        __nv_bfloat16* bBl = sm0 + 3 * MATG;
        const int off = lrow * LDSG + lseg;
#pragma unroll
        for (int j = 0; j < 4; j++) {
            st_split4(bAh, bAl, off + 4 * j, pa[j]);
            st_split4(bBh, bBl, off + 4 * j, pw[j]);
        }
    }
    __syncthreads();

    for (int kb = 0; kb < NKBG; kb++) {
        // prefetch next k-block into registers (latency hidden by MMA below)
        if (kb + 1 < NKBG) {
            const int g = (kb + 1) * 32;
#pragma unroll
            for (int j = 0; j < 4; j++) {
                pa[j] = *(const float4*)(gA + g + 4 * j);
                pw[j] = *(const float4*)(gW + g + 4 * j);
            }
        }

        // MMA on current buffer
        const __nv_bfloat16* sb  = sm0 + (kb & 1) * BUFG;
        const __nv_bfloat16* sAh = sb;
        const __nv_bfloat16* sAl = sb + MATG;
        const __nv_bfloat16* sBh = sb + 2 * MATG;
        const __nv_bfloat16* sBl = sb + 3 * MATG;
#pragma unroll
        for (int ks = 0; ks < 2; ks++) {
            const int kk = ks * 16;
            wmma::fragment<wmma::matrix_a, 16, 16, 16, __nv_bfloat16,
                           wmma::row_major> ah[2], al[2];
#pragma unroll
            for (int mt = 0; mt < 2; mt++) {
                wmma::load_matrix_sync(ah[mt], sAh + (wm * 32 + mt * 16) * LDSG + kk, LDSG);
                wmma::load_matrix_sync(al[mt], sAl + (wm * 32 + mt * 16) * LDSG + kk, LDSG);
            }
#pragma unroll
            for (int nt = 0; nt < 4; nt++) {
                wmma::fragment<wmma::matrix_b, 16, 16, 16, __nv_bfloat16,
                               wmma::col_major> bh, bl;
                wmma::load_matrix_sync(bh, sBh + (wn * 64 + nt * 16) * LDSG + kk, LDSG);
                wmma::load_matrix_sync(bl, sBl + (wn * 64 + nt * 16) * LDSG + kk, LDSG);
#pragma unroll
                for (int mt = 0; mt < 2; mt++) {
                    wmma::mma_sync(acc[mt][nt], ah[mt], bh, acc[mt][nt]);
                    wmma::mma_sync(acc[mt][nt], ah[mt], bl, acc[mt][nt]);
                    wmma::mma_sync(acc[mt][nt], al[mt], bh, acc[mt][nt]);
                }
            }
        }

        // split + store prefetched block into the other buffer
        if (kb + 1 < NKBG) {
            __nv_bfloat16* bb  = sm0 + ((kb + 1) & 1) * BUFG;
            __nv_bfloat16* bAh = bb;
            __nv_bfloat16* bAl = bb + MATG;
            __nv_bfloat16* bBh = bb + 2 * MATG;
            __nv_bfloat16* bBl = bb + 3 * MATG;
            const int off = lrow * LDSG + lseg;
#pragma unroll
            for (int j = 0; j < 4; j++) {
                st_split4(bAh, bAl, off + 4 * j, pa[j]);
                st_split4(bBh, bBl, off + 4 * j, pw[j]);
            }
            __syncthreads();
        }
    }

    // Epilogue: per-warp patch -> bias -> scatter (unchanged from R10)
    float* patch = sPatchAll + w * 320;
    const int pr = lane >> 1;
    const int pc = (lane & 1) * 8;
#pragma unroll
    for (int mt = 0; mt < 2; mt++)
#pragma unroll
        for (int nt = 0; nt < 4; nt++) {
            wmma::store_matrix_sync(patch, acc[mt][nt], 20, wmma::mem_row_major);
            __syncwarp();
            const int m = m0 + wm * 32 + mt * 16 + pr;
            const int n = n0 + wn * 64 + nt * 16 + pc;
            float4 p0 = *(const float4*)&patch[pr * 20 + pc];
            float4 p1 = *(const float4*)&patch[pr * 20 + pc + 4];
            float4 b0 = *(const float4*)&bias[n];
            float4 b1 = *(const float4*)&bias[n + 4];
            p0.x += b0.x; p0.y += b0.y; p0.z += b0.z; p0.w += b0.w;
            p1.x += b1.x; p1.y += b1.y; p1.z += b1.z; p1.w += b1.w;
            if (EPI == 0) {
                const int b_ = m >> 11, nq = m & (SEQ - 1);
                const int which = n >> 10, e = n & 1023;
                const int h = e >> 6, d = e & 63;
                float* dst = (which == 0) ? g_q : (which == 1) ? g_k : g_v;
                float* p = dst + ((((size_t)b_ * NHEADS) + h) * SEQ + nq) * HDIM + d;
                *(float4*)(p)     = p0;
                *(float4*)(p + 4) = p1;
            } else {
                float* p = C + (size_t)m * EMBED + n;
                *(float4*)(p)     = p0;
                *(float4*)(p + 4) = p1;
            }
            __syncwarp();
        }
}

// ---------------------------------------------------------------------------
// WMMA flash attention — byte-identical to Round 10 (passing).
// ---------------------------------------------------------------------------
#define OFF_QH 0
#define OFF_QL 18432
#define OFF_KH 36864
#define OFF_KL 55296
#define OFF_VH 73728
#define OFF_VL 92160
#define OFF_S  110592
#define OFF_PH 110592
#define OFF_PL 145408
#define OFF_OS 180224
#define ATTN_SMEM_BYTES 215040

__global__ __launch_bounds__(256, 1) void attn_wmma()
{
    extern __shared__ char smc[];
    __nv_bfloat16* Qh = (__nv_bfloat16*)(smc + OFF_QH);
    __nv_bfloat16* Ql = (__nv_bfloat16*)(smc + OFF_QL);
    __nv_bfloat16* Kh = (__nv_bfloat16*)(smc + OFF_KH);
    __nv_bfloat16* Kl = (__nv_bfloat16*)(smc + OFF_KL);
    __nv_bfloat16* Vh = (__nv_bfloat16*)(smc + OFF_VH);
    __nv_bfloat16* Vl = (__nv_bfloat16*)(smc + OFF_VL);
    float*         S  = (float*)        (smc + OFF_S);
    __nv_bfloat16* Ph = (__nv_bfloat16*)(smc + OFF_PH);
    __nv_bfloat16* Pl = (__nv_bfloat16*)(smc + OFF_PL);
    float*         Os = (float*)        (smc + OFF_OS);

    const int tid  = threadIdx.x;
    const int w    = tid >> 5;
    const int wm   = w & 3;
    const int wn   = w >> 2;
    const int ty   = tid >> 4;
    const int tx   = tid & 15;
    const int bh   = blockIdx.y;
    const int q0   = blockIdx.x * 128;

    const float* Qg = g_q + (size_t)bh * SEQ * HDIM;
    const float* Kg = g_k + (size_t)bh * SEQ * HDIM;
    const float* Vg = g_v + (size_t)bh * SEQ * HDIM;

#pragma unroll
    for (int i = 0; i < 8; i++) {
        int idx = tid + i * 256;
        int r   = idx >> 4;
        int c4  = (idx & 15) * 4;
        float4 v = *(const float4*)(Qg + (size_t)(q0 + r) * HDIM + c4);
        __nv_bfloat16 h, l;
        sp_bf16(v.x, h, l); Qh[r * 72 + c4 + 0] = h; Ql[r * 72 + c4 + 0] = l;
        sp_bf16(v.y, h, l); Qh[r * 72 + c4 + 1] = h; Ql[r * 72 + c4 + 1] = l;
        sp_bf16(v.z, h, l); Qh[r * 72 + c4 + 2] = h; Ql[r * 72 + c4 + 2] = l;
        sp_bf16(v.w, h, l); Qh[r * 72 + c4 + 3] = h; Ql[r * 72 + c4 + 3] = l;
    }

    float m_r[8], l_r[8], corr[8], o[8][4];
#pragma unroll
    for (int i = 0; i < 8; i++) {
        m_r[i] = -1e30f;
        l_r[i] = 0.f;
#pragma unroll
        for (int j = 0; j < 4; j++) o[i][j] = 0.f;
    }
    __syncthreads();

    for (int t = 0; t < SEQ / 128; t++) {
        const int k0 = t * 128;
#pragma unroll
        for (int i = 0; i < 8; i++) {
            int idx = tid + i * 256;
            int r   = idx >> 4;
            int c4  = (idx & 15) * 4;
            float4 kv = *(const float4*)(Kg + (size_t)(k0 + r) * HDIM + c4);
            __nv_bfloat16 h, l;
            sp_bf16(kv.x, h, l); Kh[r * 72 + c4 + 0] = h; Kl[r * 72 + c4 + 0] = l;
            sp_bf16(kv.y, h, l); Kh[r * 72 + c4 + 1] = h; Kl[r * 72 + c4 + 1] = l;
            sp_bf16(kv.z, h, l); Kh[r * 72 + c4 + 2] = h; Kl[r * 72 + c4 + 2] = l;
            sp_bf16(kv.w, h, l); Kh[r * 72 + c4 + 3] = h; Kl[r * 72 + c4 + 3] = l;
            float4 vv = *(const float4*)(Vg + (size_t)(k0 + r) * HDIM + c4);
            sp_bf16(vv.x, h, l); Vh[r * 72 + c4 + 0] = h; Vl[r * 72 + c4 + 0] = l;
            sp_bf16(vv.y, h, l); Vh[r * 72 + c4 + 1] = h; Vl[r * 72 + c4 + 1] = l;
            sp_bf16(vv.z, h, l); Vh[r * 72 + c4 + 2] = h; Vl[r * 72 + c4 + 2] = l;
            sp_bf16(vv.w, h, l); Vh[r * 72 + c4 + 3] = h; Vl[r * 72 + c4 + 3] = l;
        }
        __syncthreads();

        {
            wmma::fragment<wmma::accumulator, 16, 16, 16, float> accS[2][4];
#pragma unroll
            for (int mt = 0; mt < 2; mt++)
#pragma unroll
                for (int nt = 0; nt < 4; nt++)
                    wmma::fill_fragment(accS[mt][nt], 0.0f);

#pragma unroll
            for (int kk = 0; kk < 4; kk++) {
                const int k = kk * 16;
                wmma::fragment<wmma::matrix_a, 16, 16, 16, __nv_bfloat16,
                               wmma::row_major> ah[2], al[2];
#pragma unroll
                for (int mt = 0; mt < 2; mt++) {
                    wmma::load_matrix_sync(ah[mt], &Qh[(wm * 32 + mt * 16) * 72 + k], 72);
                    wmma::load_matrix_sync(al[mt], &Ql[(wm * 32 + mt * 16) * 72 + k], 72);
                }
#pragma unroll
                for (int nt = 0; nt < 4; nt++) {
                    wmma::fragment<wmma::matrix_b, 16, 16, 16, __nv_bfloat16,
                                   wmma::col_major> bh, bl;
                    wmma::load_matrix_sync(bh, &Kh[(wn * 64 + nt * 16) * 72 + k], 72);
                    wmma::load_matrix_sync(bl, &Kl[(wn * 64 + nt * 16) * 72 + k], 72);
#pragma unroll
                    for (int mt = 0; mt < 2; mt++) {
                        wmma::mma_sync(accS[mt][nt], ah[mt], bh, accS[mt][nt]);
                        wmma::mma_sync(accS[mt][nt], ah[mt], bl, accS[mt][nt]);
                        wmma::mma_sync(accS[mt][nt], al[mt], bh, accS[mt][nt]);
                    }
                }
            }
#pragma unroll
            for (int mt = 0; mt < 2; mt++)
#pragma unroll
                for (int nt = 0; nt < 4; nt++)
                    wmma::store_matrix_sync(
                        &S[(wm * 32 + mt * 16) * 136 + wn * 64 + nt * 16],
                        accS[mt][nt], 136, wmma::mem_row_major);
        }
        __syncthreads();

        float s[8][8];
#pragma unroll
        for (int r = 0; r < 8; r++) {
            *(float4*)&s[r][0] = *(const float4*)&S[(ty * 8 + r) * 136 + tx * 8];
            *(float4*)&s[r][4] = *(const float4*)&S[(ty * 8 + r) * 136 + tx * 8 + 4];
        }
#pragma unroll
        for (int r = 0; r < 8; r++) {
            float tmax = -1e30f;
#pragma unroll
            for (int c = 0; c < 8; c++) {
                s[r][c] *= 0.125f;
                tmax = fmaxf(tmax, s[r][c]);
            }
#pragma unroll
            for (int off = 8; off; off >>= 1)
                tmax = fmaxf(tmax, __shfl_xor_sync(0xffffffffu, tmax, off));
            float mnew = fmaxf(m_r[r], tmax);
            corr[r] = __expf(m_r[r] - mnew);
            m_r[r] = mnew;
            float rsum = 0.f;
#pragma unroll
            for (int c = 0; c < 8; c++) {
                float p = __expf(s[r][c] - mnew);
                s[r][c] = p;
                rsum += p;
            }
#pragma unroll
            for (int off = 8; off; off >>= 1)
                rsum += __shfl_xor_sync(0xffffffffu, rsum, off);
            l_r[r] = l_r[r] * corr[r] + rsum;
        }
        __syncthreads();

#pragma unroll
        for (int r = 0; r < 8; r++)
#pragma unroll
            for (int c = 0; c < 8; c++) {
                __nv_bfloat16 h, l;
                sp_bf16(s[r][c], h, l);
                Ph[(ty * 8 + r) * 136 + tx * 8 + c] = h;
                Pl[(ty * 8 + r) * 136 + tx * 8 + c] = l;
            }
        __syncthreads();

        {
            wmma::fragment<wmma::accumulator, 16, 16, 16, float> accO[2][2];
#pragma unroll
            for (int mt = 0; mt < 2; mt++)
#pragma unroll
                for (int nt = 0; nt < 2; nt++)
                    wmma::fill_fragment(accO[mt][nt], 0.0f);

#pragma unroll
            for (int kk = 0; kk < 8; kk++) {
                const int k = kk * 16;
                wmma::fragment<wmma::matrix_a, 16, 16, 16, __nv_bfloat16,
                               wmma::row_major> ph[2], pl[2];
#pragma unroll
                for (int mt = 0; mt < 2; mt++) {
                    wmma::load_matrix_sync(ph[mt], &Ph[(wm * 32 + mt * 16) * 136 + k], 136);
                    wmma::load_matrix_sync(pl[mt], &Pl[(wm * 32 + mt * 16) * 136 + k], 136);
                }
#pragma unroll
                for (int nt = 0; nt < 2; nt++) {
                    wmma::fragment<wmma::matrix_b, 16, 16, 16, __nv_bfloat16,
                                   wmma::row_major> vbh, vbl;
                    wmma::load_matrix_sync(vbh, &Vh[k * 72 + wn * 32 + nt * 16], 72);
                    wmma::load_matrix_sync(vbl, &Vl[k * 72 + wn * 32 + nt * 16], 72);
#pragma unroll
                    for (int mt = 0; mt < 2; mt++) {
                        wmma::mma_sync(accO[mt][nt], ph[mt], vbh, accO[mt][nt]);
                        wmma::mma_sync(accO[mt][nt], ph[mt], vbl, accO[mt][nt]);
                        wmma::mma_sync(accO[mt][nt], pl[mt], vbh, accO[mt][nt]);
                    }
                }
            }
#pragma unroll
            for (int mt = 0; mt < 2; mt++)
#pragma unroll
                for (int nt = 0; nt < 2; nt++)
                    wmma::store_matrix_sync(
                        &Os[(wm * 32 + mt * 16) * 68 + wn * 32 + nt * 16],
                        accO[mt][nt], 68, wmma::mem_row_major);
        }
        __syncthreads();

#pragma unroll
        for (int r = 0; r < 8; r++) {
            float4 pv = *(const float4*)&Os[(ty * 8 + r) * 68 + tx * 4];
            o[r][0] = o[r][0] * corr[r] + pv.x;
            o[r][1] = o[r][1] * corr[r] + pv.y;
            o[r][2] = o[r][2] * corr[r] + pv.z;
            o[r][3] = o[r][3] * corr[r] + pv.w;
        }
        __syncthreads();
    }

    const int b_ = bh >> 4;
    const int h  = bh & 15;
#pragma unroll
    for (int r = 0; r < 8; r++) {
        float inv = 1.0f / l_r[r];
        int n = q0 + ty * 8 + r;
        float4 v = make_float4(o[r][0] * inv, o[r][1] * inv,
                               o[r][2] * inv, o[r][3] * inv);
        *(float4*)(g_attn + ((size_t)b_ * SEQ + n) * EMBED + h * 64 + tx * 4) = v;
    }
}

// ---------------------------------------------------------------------------
extern "C" void kernel_launch(void* const* d_in, const int* in_sizes, int n_in,
                              void* d_out, int out_size)
{
    (void)in_sizes; (void)n_in; (void)out_size;
    const float* x     = (const float*)d_in[0];
    const float* qkv_w = (const float*)d_in[1];
    const float* qkv_b = (const float*)d_in[2];
    const float* out_w = (const float*)d_in[3];
    const float* out_b = (const float*)d_in[4];
    float* out = (float*)d_out;

    cudaFuncSetAttribute(gemm_wmma<0>,
                         cudaFuncAttributeMaxDynamicSharedMemorySize, GEMM_SMEM);
    cudaFuncSetAttribute(gemm_wmma<1>,
                         cudaFuncAttributeMaxDynamicSharedMemorySize, GEMM_SMEM);
    cudaFuncSetAttribute(attn_wmma,
                         cudaFuncAttributeMaxDynamicSharedMemorySize,
                         ATTN_SMEM_BYTES);

    // 1) QKV projection (WMMA bf16x3, prefetch-pipelined) + scatter
    gemm_wmma<0><<<dim3(3 * EMBED / 128, MTOK / 128), 256, GEMM_SMEM>>>(
        x, qkv_w, qkv_b, nullptr);
    // 2) Flash attention (WMMA bf16x3 + fp32 softmax) -> g_attn
    attn_wmma<<<dim3(SEQ / 128, BATCH * NHEADS), 256, ATTN_SMEM_BYTES>>>();
    // 3) Output projection (WMMA bf16x3, prefetch-pipelined)
    gemm_wmma<1><<<dim3(EMBED / 128, MTOK / 128), 256, GEMM_SMEM>>>(
        nullptr, out_w, out_b, out);
}

// round 13
// speedup vs baseline: 1.7228x; 1.0343x over previous
#include <cuda_runtime.h>
#include <cuda_bf16.h>
#include <mma.h>
#include <cstdint>

using namespace nvcuda;

// Problem constants
#define EMBED  1024
#define NHEADS 16
#define HDIM   64
#define BATCH  4
#define SEQ    2048
#define MTOK   (BATCH * SEQ)   // 8192
#define QKV_PLANE (BATCH * NHEADS * SEQ * HDIM)   // 8388608 elems
#define ATT_PLANE (MTOK * EMBED)                  // 8388608 elems

// ---------------------------------------------------------------------------
// Scratch — EXACTLY the proven-safe 128 MB footprint. Planes are recycled:
//  g_q/g_k/g_v: QKV output as bf16 hi[0:8M) / lo[8M:16M) planes
//  g_attn:      (phase 1) qkv_w hi/lo planes; (phase 2) attn-out hi/lo planes
//  g_q again:   (phase 3, after attn) out_w hi/lo planes
// ---------------------------------------------------------------------------
__device__ float g_q[QKV_PLANE];
__device__ float g_k[QKV_PLANE];
__device__ float g_v[QKV_PLANE];
__device__ float g_attn[ATT_PLANE];

__device__ __forceinline__ void sp_bf16(float x, __nv_bfloat16& h, __nv_bfloat16& l)
{
    h = __float2bfloat16_rn(x);
    l = __float2bfloat16_rn(x - __bfloat162float(h));
}

// split a float4 and store 4 hi + 4 lo bf16 at H/L + off (smem path)
__device__ __forceinline__ void st_split4(
    __nv_bfloat16* H, __nv_bfloat16* L, int off, float4 v)
{
    __nv_bfloat16 hx, lx, hy, ly, hz, lz, hw, lw;
    sp_bf16(v.x, hx, lx); sp_bf16(v.y, hy, ly);
    sp_bf16(v.z, hz, lz); sp_bf16(v.w, hw, lw);
    *(__nv_bfloat162*)(H + off)     = __nv_bfloat162(hx, hy);
    *(__nv_bfloat162*)(H + off + 2) = __nv_bfloat162(hz, hw);
    *(__nv_bfloat162*)(L + off)     = __nv_bfloat162(lx, ly);
    *(__nv_bfloat162*)(L + off + 2) = __nv_bfloat162(lz, lw);
}

// ---------------------------------------------------------------------------
// Weight split: fp32 -> bf16 hi/lo planes (4 elems/thread).
// ---------------------------------------------------------------------------
__global__ __launch_bounds__(256) void split_w(
    const float* __restrict__ src,
    __nv_bfloat16* __restrict__ hp, __nv_bfloat16* __restrict__ lp)
{
    int i = blockIdx.x * 256 + threadIdx.x;
    float4 v = ((const float4*)src)[i];
    st_split4(hp, lp, 4 * i, v);
}

// ---------------------------------------------------------------------------
// QKV GEMM: A = x fp32 (split in-kernel), B = pre-split W planes.
// C[m][n] = sum_k A[m][k]*W[n][k] + bias[n]; epilogue writes bf16 hi/lo
// planes into g_q/g_k/g_v. Block 128x128, BK=32, reg-prefetch + double buf.
// ---------------------------------------------------------------------------
#define LDSG  40
#define MATG  (128 * LDSG)
#define BUFG  (4 * MATG)
#define GEMM_SMEM (2 * BUFG * 2 + 8 * 16 * 20 * 4)   // 92160 B
#define NKBG  (EMBED / 32)

__global__ __launch_bounds__(256) void gemm_qkv(
    const float* __restrict__ A, const __nv_bfloat16* __restrict__ Wh,
    const float* __restrict__ bias)
{
    extern __shared__ __align__(16) char dsm[];
    __nv_bfloat16* sm0 = (__nv_bfloat16*)dsm;
    float* sPatchAll   = (float*)(dsm + 2 * BUFG * 2);

    const __nv_bfloat16* Wl = Wh + 3 * EMBED * EMBED;

    const int tid  = threadIdx.x;
    const int lane = tid & 31;
    const int w    = tid >> 5;
    const int wm   = w & 3;
    const int wn   = w >> 2;
    const int m0   = blockIdx.y * 128;
    const int n0   = blockIdx.x * 128;

    const int lrow = tid >> 1;
    const int lseg = (tid & 1) * 16;
    const float* gA = A + (size_t)(m0 + lrow) * EMBED + lseg;
    const __nv_bfloat16* gWh = Wh + (size_t)(n0 + lrow) * EMBED + lseg;
    const __nv_bfloat16* gWl = Wl + (size_t)(n0 + lrow) * EMBED + lseg;

    wmma::fragment<wmma::accumulator, 16, 16, 16, float> acc[2][4];
#pragma unroll
    for (int mt = 0; mt < 2; mt++)
#pragma unroll
        for (int nt = 0; nt < 4; nt++)
            wmma::fill_fragment(acc[mt][nt], 0.0f);

    float4 pa[4];
    uint4  ph[2], pl[2];

#pragma unroll
    for (int j = 0; j < 4; j++) pa[j] = *(const float4*)(gA + 4 * j);
    ph[0] = *(const uint4*)(gWh);     ph[1] = *(const uint4*)(gWh + 8);
    pl[0] = *(const uint4*)(gWl);     pl[1] = *(const uint4*)(gWl + 8);
    {
        __nv_bfloat16* bAh = sm0;
        __nv_bfloat16* bAl = sm0 + MATG;
        __nv_bfloat16* bBh = sm0 + 2 * MATG;
        __nv_bfloat16* bBl = sm0 + 3 * MATG;
        const int off = lrow * LDSG + lseg;
#pragma unroll
        for (int j = 0; j < 4; j++) st_split4(bAh, bAl, off + 4 * j, pa[j]);
        *(uint4*)(bBh + off) = ph[0];  *(uint4*)(bBh + off + 8) = ph[1];
        *(uint4*)(bBl + off) = pl[0];  *(uint4*)(bBl + off + 8) = pl[1];
    }
    __syncthreads();

    for (int kb = 0; kb < NKBG; kb++) {
        if (kb + 1 < NKBG) {
            const int g = (kb + 1) * 32;
#pragma unroll
            for (int j = 0; j < 4; j++) pa[j] = *(const float4*)(gA + g + 4 * j);
            ph[0] = *(const uint4*)(gWh + g);  ph[1] = *(const uint4*)(gWh + g + 8);
            pl[0] = *(const uint4*)(gWl + g);  pl[1] = *(const uint4*)(gWl + g + 8);
        }

        const __nv_bfloat16* sb  = sm0 + (kb & 1) * BUFG;
        const __nv_bfloat16* sAh = sb;
        const __nv_bfloat16* sAl = sb + MATG;
        const __nv_bfloat16* sBh = sb + 2 * MATG;
        const __nv_bfloat16* sBl = sb + 3 * MATG;
#pragma unroll
        for (int ks = 0; ks < 2; ks++) {
            const int kk = ks * 16;
            wmma::fragment<wmma::matrix_a, 16, 16, 16, __nv_bfloat16,
                           wmma::row_major> ah[2], al[2];
#pragma unroll
            for (int mt = 0; mt < 2; mt++) {
                wmma::load_matrix_sync(ah[mt], sAh + (wm * 32 + mt * 16) * LDSG + kk, LDSG);
                wmma::load_matrix_sync(al[mt], sAl + (wm * 32 + mt * 16) * LDSG + kk, LDSG);
            }
#pragma unroll
            for (int nt = 0; nt < 4; nt++) {
                wmma::fragment<wmma::matrix_b, 16, 16, 16, __nv_bfloat16,
                               wmma::col_major> bh, bl;
                wmma::load_matrix_sync(bh, sBh + (wn * 64 + nt * 16) * LDSG + kk, LDSG);
                wmma::load_matrix_sync(bl, sBl + (wn * 64 + nt * 16) * LDSG + kk, LDSG);
#pragma unroll
                for (int mt = 0; mt < 2; mt++) {
                    wmma::mma_sync(acc[mt][nt], ah[mt], bh, acc[mt][nt]);
                    wmma::mma_sync(acc[mt][nt], ah[mt], bl, acc[mt][nt]);
                    wmma::mma_sync(acc[mt][nt], al[mt], bh, acc[mt][nt]);
                }
            }
        }

        if (kb + 1 < NKBG) {
            __nv_bfloat16* bb  = sm0 + ((kb + 1) & 1) * BUFG;
            __nv_bfloat16* bAh = bb;
            __nv_bfloat16* bAl = bb + MATG;
            __nv_bfloat16* bBh = bb + 2 * MATG;
            __nv_bfloat16* bBl = bb + 3 * MATG;
            const int off = lrow * LDSG + lseg;
#pragma unroll
            for (int j = 0; j < 4; j++) st_split4(bAh, bAl, off + 4 * j, pa[j]);
            *(uint4*)(bBh + off) = ph[0];  *(uint4*)(bBh + off + 8) = ph[1];
            *(uint4*)(bBl + off) = pl[0];  *(uint4*)(bBl + off + 8) = pl[1];
            __syncthreads();
        }
    }

    // Epilogue: bias add, then write bf16 hi/lo planes into g_q/g_k/g_v
    float* patch = sPatchAll + w * 320;
    const int pr = lane >> 1;
    const int pc = (lane & 1) * 8;
#pragma unroll
    for (int mt = 0; mt < 2; mt++)
#pragma unroll
        for (int nt = 0; nt < 4; nt++) {
            wmma::store_matrix_sync(patch, acc[mt][nt], 20, wmma::mem_row_major);
            __syncwarp();
            const int m = m0 + wm * 32 + mt * 16 + pr;
            const int n = n0 + wn * 64 + nt * 16 + pc;
            float f[8];
#pragma unroll
            for (int j = 0; j < 8; j++)
                f[j] = patch[pr * 20 + pc + j] + bias[n + j];
            const int b_ = m >> 11, nq = m & (SEQ - 1);
            const int which = n >> 10, e = n & 1023;
            const int h = e >> 6, d = e & 63;
            float* base = (which == 0) ? g_q : (which == 1) ? g_k : g_v;
            __nv_bfloat16* hp = (__nv_bfloat16*)base;
            __nv_bfloat16* lp = hp + QKV_PLANE;
            const size_t off = ((((size_t)b_ * NHEADS) + h) * SEQ + nq) * HDIM + d;
#pragma unroll
            for (int j = 0; j < 8; j += 2) {
                __nv_bfloat16 h0, l0, h1, l1;
                sp_bf16(f[j], h0, l0);
                sp_bf16(f[j + 1], h1, l1);
                *(__nv_bfloat162*)(hp + off + j) = __nv_bfloat162(h0, h1);
                *(__nv_bfloat162*)(lp + off + j) = __nv_bfloat162(l0, l1);
            }
            __syncwarp();
        }
}

// ---------------------------------------------------------------------------
// Output-proj GEMM: BOTH operands pre-split planes; zero conversions in loop.
// ---------------------------------------------------------------------------
__global__ __launch_bounds__(256) void gemm_proj(
    const __nv_bfloat16* __restrict__ Ah, const __nv_bfloat16* __restrict__ Wh,
    const float* __restrict__ bias, float* __restrict__ C)
{
    extern __shared__ __align__(16) char dsm[];
    __nv_bfloat16* sm0 = (__nv_bfloat16*)dsm;
    float* sPatchAll   = (float*)(dsm + 2 * BUFG * 2);

    const __nv_bfloat16* Al = Ah + ATT_PLANE;
    const __nv_bfloat16* Wl = Wh + EMBED * EMBED;

    const int tid  = threadIdx.x;
    const int lane = tid & 31;
    const int w    = tid >> 5;
    const int wm   = w & 3;
    const int wn   = w >> 2;
    const int m0   = blockIdx.y * 128;
    const int n0   = blockIdx.x * 128;

    const int lrow = tid >> 1;
    const int lseg = (tid & 1) * 16;
    const __nv_bfloat16* gAh = Ah + (size_t)(m0 + lrow) * EMBED + lseg;
    const __nv_bfloat16* gAl = Al + (size_t)(m0 + lrow) * EMBED + lseg;
    const __nv_bfloat16* gWh = Wh + (size_t)(n0 + lrow) * EMBED + lseg;
    const __nv_bfloat16* gWl = Wl + (size_t)(n0 + lrow) * EMBED + lseg;

    wmma::fragment<wmma::accumulator, 16, 16, 16, float> acc[2][4];
#pragma unroll
    for (int mt = 0; mt < 2; mt++)
#pragma unroll
        for (int nt = 0; nt < 4; nt++)
            wmma::fill_fragment(acc[mt][nt], 0.0f);

    uint4 p0, p1, p2, p3, p4, p5, p6, p7;
    p0 = *(const uint4*)(gAh);  p1 = *(const uint4*)(gAh + 8);
    p2 = *(const uint4*)(gAl);  p3 = *(const uint4*)(gAl + 8);
    p4 = *(const uint4*)(gWh);  p5 = *(const uint4*)(gWh + 8);
    p6 = *(const uint4*)(gWl);  p7 = *(const uint4*)(gWl + 8);
    {
        __nv_bfloat16* b = sm0;
        const int off = lrow * LDSG + lseg;
        *(uint4*)(b + off) = p0;               *(uint4*)(b + off + 8) = p1;
        *(uint4*)(b + MATG + off) = p2;        *(uint4*)(b + MATG + off + 8) = p3;
        *(uint4*)(b + 2 * MATG + off) = p4;    *(uint4*)(b + 2 * MATG + off + 8) = p5;
        *(uint4*)(b + 3 * MATG + off) = p6;    *(uint4*)(b + 3 * MATG + off + 8) = p7;
    }
    __syncthreads();

    for (int kb = 0; kb < NKBG; kb++) {
        if (kb + 1 < NKBG) {
            const int g = (kb + 1) * 32;
            p0 = *(const uint4*)(gAh + g);  p1 = *(const uint4*)(gAh + g + 8);
            p2 = *(const uint4*)(gAl + g);  p3 = *(const uint4*)(gAl + g + 8);
            p4 = *(const uint4*)(gWh + g);  p5 = *(const uint4*)(gWh + g + 8);
            p6 = *(const uint4*)(gWl + g);  p7 = *(const uint4*)(gWl + g + 8);
        }

        const __nv_bfloat16* sb  = sm0 + (kb & 1) * BUFG;
        const __nv_bfloat16* sAh = sb;
        const __nv_bfloat16* sAl = sb + MATG;
        const __nv_bfloat16* sBh = sb + 2 * MATG;
        const __nv_bfloat16* sBl = sb + 3 * MATG;
#pragma unroll
        for (int ks = 0; ks < 2; ks++) {
            const int kk = ks * 16;
            wmma::fragment<wmma::matrix_a, 16, 16, 16, __nv_bfloat16,
                           wmma::row_major> ah[2], al[2];
#pragma unroll
            for (int mt = 0; mt < 2; mt++) {
                wmma::load_matrix_sync(ah[mt], sAh + (wm * 32 + mt * 16) * LDSG + kk, LDSG);
                wmma::load_matrix_sync(al[mt], sAl + (wm * 32 + mt * 16) * LDSG + kk, LDSG);
            }
#pragma unroll
            for (int nt = 0; nt < 4; nt++) {
                wmma::fragment<wmma::matrix_b, 16, 16, 16, __nv_bfloat16,
                               wmma::col_major> bh, bl;
                wmma::load_matrix_sync(bh, sBh + (wn * 64 + nt * 16) * LDSG + kk, LDSG);
                wmma::load_matrix_sync(bl, sBl + (wn * 64 + nt * 16) * LDSG + kk, LDSG);
#pragma unroll
                for (int mt = 0; mt < 2; mt++) {
                    wmma::mma_sync(acc[mt][nt], ah[mt], bh, acc[mt][nt]);
                    wmma::mma_sync(acc[mt][nt], ah[mt], bl, acc[mt][nt]);
                    wmma::mma_sync(acc[mt][nt], al[mt], bh, acc[mt][nt]);
                }
            }
        }

        if (kb + 1 < NKBG) {
            __nv_bfloat16* b = sm0 + ((kb + 1) & 1) * BUFG;
            const int off = lrow * LDSG + lseg;
            *(uint4*)(b + off) = p0;               *(uint4*)(b + off + 8) = p1;
            *(uint4*)(b + MATG + off) = p2;        *(uint4*)(b + MATG + off + 8) = p3;
            *(uint4*)(b + 2 * MATG + off) = p4;    *(uint4*)(b + 2 * MATG + off + 8) = p5;
            *(uint4*)(b + 3 * MATG + off) = p6;    *(uint4*)(b + 3 * MATG + off + 8) = p7;
            __syncthreads();
        }
    }

    float* patch = sPatchAll + w * 320;
    const int pr = lane >> 1;
    const int pc = (lane & 1) * 8;
#pragma unroll
    for (int mt = 0; mt < 2; mt++)
#pragma unroll
        for (int nt = 0; nt < 4; nt++) {
            wmma::store_matrix_sync(patch, acc[mt][nt], 20, wmma::mem_row_major);
            __syncwarp();
            const int m = m0 + wm * 32 + mt * 16 + pr;
            const int n = n0 + wn * 64 + nt * 16 + pc;
            float4 q0 = *(const float4*)&patch[pr * 20 + pc];
            float4 q1 = *(const float4*)&patch[pr * 20 + pc + 4];
            float4 b0 = *(const float4*)&bias[n];
            float4 b1 = *(const float4*)&bias[n + 4];
            q0.x += b0.x; q0.y += b0.y; q0.z += b0.z; q0.w += b0.w;
            q1.x += b1.x; q1.y += b1.y; q1.z += b1.z; q1.w += b1.w;
            float* p = C + (size_t)m * EMBED + n;
            *(float4*)(p)     = q0;
            *(float4*)(p + 4) = q1;
            __syncwarp();
        }
}

// ---------------------------------------------------------------------------
// WMMA flash attention — R12 core; loaders read pre-split planes (pure
// copies), epilogue writes bf16 hi/lo planes into g_attn.
// ---------------------------------------------------------------------------
#define OFF_QH 0
#define OFF_QL 18432
#define OFF_KH 36864
#define OFF_KL 55296
#define OFF_VH 73728
#define OFF_VL 92160
#define OFF_S  110592
#define OFF_PH 110592
#define OFF_PL 145408
#define OFF_OS 180224
#define ATTN_SMEM_BYTES 215040

__global__ __launch_bounds__(256, 1) void attn_wmma()
{
    extern __shared__ char smc[];
    __nv_bfloat16* Qh = (__nv_bfloat16*)(smc + OFF_QH);
    __nv_bfloat16* Ql = (__nv_bfloat16*)(smc + OFF_QL);
    __nv_bfloat16* Kh = (__nv_bfloat16*)(smc + OFF_KH);
    __nv_bfloat16* Kl = (__nv_bfloat16*)(smc + OFF_KL);
    __nv_bfloat16* Vh = (__nv_bfloat16*)(smc + OFF_VH);
    __nv_bfloat16* Vl = (__nv_bfloat16*)(smc + OFF_VL);
    float*         S  = (float*)        (smc + OFF_S);
    __nv_bfloat16* Ph = (__nv_bfloat16*)(smc + OFF_PH);
    __nv_bfloat16* Pl = (__nv_bfloat16*)(smc + OFF_PL);
    float*         Os = (float*)        (smc + OFF_OS);

    const int tid  = threadIdx.x;
    const int w    = tid >> 5;
    const int wm   = w & 3;
    const int wn   = w >> 2;
    const int ty   = tid >> 4;
    const int tx   = tid & 15;
    const int bh   = blockIdx.y;
    const int q0   = blockIdx.x * 128;

    const __nv_bfloat16* qh = (const __nv_bfloat16*)g_q;
    const __nv_bfloat16* kh = (const __nv_bfloat16*)g_k;
    const __nv_bfloat16* vh = (const __nv_bfloat16*)g_v;
    const size_t tb = (size_t)bh * SEQ * HDIM;

    // Q tile: pure plane copies (uint4 = 8 bf16)
#pragma unroll
    for (int i = 0; i < 4; i++) {
        int idx = tid + i * 256;
        int r   = idx >> 3;
        int c8  = (idx & 7) * 8;
        size_t g = tb + (size_t)(q0 + r) * HDIM + c8;
        *(uint4*)(Qh + r * 72 + c8) = *(const uint4*)(qh + g);
        *(uint4*)(Ql + r * 72 + c8) = *(const uint4*)(qh + QKV_PLANE + g);
    }

    float m_r[8], l_r[8], corr[8], o[8][4];
#pragma unroll
    for (int i = 0; i < 8; i++) {
        m_r[i] = -1e30f;
        l_r[i] = 0.f;
#pragma unroll
        for (int j = 0; j < 4; j++) o[i][j] = 0.f;
    }
    __syncthreads();

    for (int t = 0; t < SEQ / 128; t++) {
        const int k0 = t * 128;
#pragma unroll
        for (int i = 0; i < 4; i++) {
            int idx = tid + i * 256;
            int r   = idx >> 3;
            int c8  = (idx & 7) * 8;
            size_t g = tb + (size_t)(k0 + r) * HDIM + c8;
            *(uint4*)(Kh + r * 72 + c8) = *(const uint4*)(kh + g);
            *(uint4*)(Kl + r * 72 + c8) = *(const uint4*)(kh + QKV_PLANE + g);
            *(uint4*)(Vh + r * 72 + c8) = *(const uint4*)(vh + g);
            *(uint4*)(Vl + r * 72 + c8) = *(const uint4*)(vh + QKV_PLANE + g);
        }
        __syncthreads();

        {
            wmma::fragment<wmma::accumulator, 16, 16, 16, float> accS[2][4];
#pragma unroll
            for (int mt = 0; mt < 2; mt++)
#pragma unroll
                for (int nt = 0; nt < 4; nt++)
                    wmma::fill_fragment(accS[mt][nt], 0.0f);

#pragma unroll
            for (int kk = 0; kk < 4; kk++) {
                const int k = kk * 16;
                wmma::fragment<wmma::matrix_a, 16, 16, 16, __nv_bfloat16,
                               wmma::row_major> ah[2], al[2];
#pragma unroll
                for (int mt = 0; mt < 2; mt++) {
                    wmma::load_matrix_sync(ah[mt], &Qh[(wm * 32 + mt * 16) * 72 + k], 72);
                    wmma::load_matrix_sync(al[mt], &Ql[(wm * 32 + mt * 16) * 72 + k], 72);
                }
#pragma unroll
                for (int nt = 0; nt < 4; nt++) {
                    wmma::fragment<wmma::matrix_b, 16, 16, 16, __nv_bfloat16,
                                   wmma::col_major> bh2, bl2;
                    wmma::load_matrix_sync(bh2, &Kh[(wn * 64 + nt * 16) * 72 + k], 72);
                    wmma::load_matrix_sync(bl2, &Kl[(wn * 64 + nt * 16) * 72 + k], 72);
#pragma unroll
                    for (int mt = 0; mt < 2; mt++) {
                        wmma::mma_sync(accS[mt][nt], ah[mt], bh2, accS[mt][nt]);
                        wmma::mma_sync(accS[mt][nt], ah[mt], bl2, accS[mt][nt]);
                        wmma::mma_sync(accS[mt][nt], al[mt], bh2, accS[mt][nt]);
                    }
                }
            }
#pragma unroll
            for (int mt = 0; mt < 2; mt++)
#pragma unroll
                for (int nt = 0; nt < 4; nt++)
                    wmma::store_matrix_sync(
                        &S[(wm * 32 + mt * 16) * 136 + wn * 64 + nt * 16],
                        accS[mt][nt], 136, wmma::mem_row_major);
        }
        __syncthreads();

        float s[8][8];
#pragma unroll
        for (int r = 0; r < 8; r++) {
            *(float4*)&s[r][0] = *(const float4*)&S[(ty * 8 + r) * 136 + tx * 8];
            *(float4*)&s[r][4] = *(const float4*)&S[(ty * 8 + r) * 136 + tx * 8 + 4];
        }
#pragma unroll
        for (int r = 0; r < 8; r++) {
            float tmax = -1e30f;
#pragma unroll
            for (int c = 0; c < 8; c++) {
                s[r][c] *= 0.125f;
                tmax = fmaxf(tmax, s[r][c]);
            }
#pragma unroll
            for (int off = 8; off; off >>= 1)
                tmax = fmaxf(tmax, __shfl_xor_sync(0xffffffffu, tmax, off));
            float mnew = fmaxf(m_r[r], tmax);
            corr[r] = __expf(m_r[r] - mnew);
            m_r[r] = mnew;
            float rsum = 0.f;
#pragma unroll
            for (int c = 0; c < 8; c++) {
                float p = __expf(s[r][c] - mnew);
                s[r][c] = p;
                rsum += p;
            }
#pragma unroll
            for (int off = 8; off; off >>= 1)
                rsum += __shfl_xor_sync(0xffffffffu, rsum, off);
            l_r[r] = l_r[r] * corr[r] + rsum;
        }
        __syncthreads();

#pragma unroll
        for (int r = 0; r < 8; r++)
#pragma unroll
            for (int c = 0; c < 8; c++) {
                __nv_bfloat16 h, l;
                sp_bf16(s[r][c], h, l);
                Ph[(ty * 8 + r) * 136 + tx * 8 + c] = h;
                Pl[(ty * 8 + r) * 136 + tx * 8 + c] = l;
            }
        __syncthreads();

        {
            wmma::fragment<wmma::accumulator, 16, 16, 16, float> accO[2][2];
#pragma unroll
            for (int mt = 0; mt < 2; mt++)
#pragma unroll
                for (int nt = 0; nt < 2; nt++)
                    wmma::fill_fragment(accO[mt][nt], 0.0f);

#pragma unroll
            for (int kk = 0; kk < 8; kk++) {
                const int k = kk * 16;
                wmma::fragment<wmma::matrix_a, 16, 16, 16, __nv_bfloat16,
                               wmma::row_major> ph[2], pl[2];
#pragma unroll
                for (int mt = 0; mt < 2; mt++) {
                    wmma::load_matrix_sync(ph[mt], &Ph[(wm * 32 + mt * 16) * 136 + k], 136);
                    wmma::load_matrix_sync(pl[mt], &Pl[(wm * 32 + mt * 16) * 136 + k], 136);
                }
#pragma unroll
                for (int nt = 0; nt < 2; nt++) {
                    wmma::fragment<wmma::matrix_b, 16, 16, 16, __nv_bfloat16,
                                   wmma::row_major> vbh, vbl;
                    wmma::load_matrix_sync(vbh, &Vh[k * 72 + wn * 32 + nt * 16], 72);
                    wmma::load_matrix_sync(vbl, &Vl[k * 72 + wn * 32 + nt * 16], 72);
#pragma unroll
                    for (int mt = 0; mt < 2; mt++) {
                        wmma::mma_sync(accO[mt][nt], ph[mt], vbh, accO[mt][nt]);
                        wmma::mma_sync(accO[mt][nt], ph[mt], vbl, accO[mt][nt]);
                        wmma::mma_sync(accO[mt][nt], pl[mt], vbh, accO[mt][nt]);
                    }
                }
            }
#pragma unroll
            for (int mt = 0; mt < 2; mt++)
#pragma unroll
                for (int nt = 0; nt < 2; nt++)
                    wmma::store_matrix_sync(
                        &Os[(wm * 32 + mt * 16) * 68 + wn * 32 + nt * 16],
                        accO[mt][nt], 68, wmma::mem_row_major);
        }
        __syncthreads();

#pragma unroll
        for (int r = 0; r < 8; r++) {
            float4 pv = *(const float4*)&Os[(ty * 8 + r) * 68 + tx * 4];
            o[r][0] = o[r][0] * corr[r] + pv.x;
            o[r][1] = o[r][1] * corr[r] + pv.y;
            o[r][2] = o[r][2] * corr[r] + pv.z;
            o[r][3] = o[r][3] * corr[r] + pv.w;
        }
        __syncthreads();
    }

    // Finalize -> hi/lo planes in g_attn
    const int b_ = bh >> 4;
    const int hh = bh & 15;
    __nv_bfloat16* oh = (__nv_bfloat16*)g_attn;
    __nv_bfloat16* ol = oh + ATT_PLANE;
#pragma unroll
    for (int r = 0; r < 8; r++) {
        float inv = 1.0f / l_r[r];
        int n = q0 + ty * 8 + r;
        const size_t off = ((size_t)b_ * SEQ + n) * EMBED + hh * 64 + tx * 4;
        float v0 = o[r][0] * inv, v1 = o[r][1] * inv;
        float v2 = o[r][2] * inv, v3 = o[r][3] * inv;
        __nv_bfloat16 h0, l0, h1, l1, h2, l2, h3, l3;
        sp_bf16(v0, h0, l0); sp_bf16(v1, h1, l1);
        sp_bf16(v2, h2, l2); sp_bf16(v3, h3, l3);
        *(__nv_bfloat162*)(oh + off)     = __nv_bfloat162(h0, h1);
        *(__nv_bfloat162*)(oh + off + 2) = __nv_bfloat162(h2, h3);
        *(__nv_bfloat162*)(ol + off)     = __nv_bfloat162(l0, l1);
        *(__nv_bfloat162*)(ol + off + 2) = __nv_bfloat162(l2, l3);
    }
}

// ---------------------------------------------------------------------------
extern "C" void kernel_launch(void* const* d_in, const int* in_sizes, int n_in,
                              void* d_out, int out_size)
{
    (void)in_sizes; (void)n_in; (void)out_size;
    const float* x     = (const float*)d_in[0];
    const float* qkv_w = (const float*)d_in[1];
    const float* qkv_b = (const float*)d_in[2];
    const float* out_w = (const float*)d_in[3];
    const float* out_b = (const float*)d_in[4];
    float* out = (float*)d_out;

    cudaFuncSetAttribute(gemm_qkv,
                         cudaFuncAttributeMaxDynamicSharedMemorySize, GEMM_SMEM);
    cudaFuncSetAttribute(gemm_proj,
                         cudaFuncAttributeMaxDynamicSharedMemorySize, GEMM_SMEM);
    cudaFuncSetAttribute(attn_wmma,
                         cudaFuncAttributeMaxDynamicSharedMemorySize,
                         ATTN_SMEM_BYTES);

    // 0) split qkv_w into hi/lo planes parked in g_attn (12 MB of 32 MB)
    __nv_bfloat16* wq_planes = (__nv_bfloat16*)(void*)g_attn;   // host-side symbol math done on device side via pointers below
    // note: device symbol addresses are resolved inside kernels; here we only
    // pass the base through a kernel parameter obtained from the symbol:
    // simplest portable route — use cudaGetSymbolAddress once (not an alloc).
    static void* p_attn = nullptr;
    static void* p_q = nullptr;
    if (!p_attn) {
        cudaGetSymbolAddress(&p_attn, g_attn);
        cudaGetSymbolAddress(&p_q, g_q);
    }
    __nv_bfloat16* wq_h = (__nv_bfloat16*)p_attn;
    __nv_bfloat16* wq_l = wq_h + 3 * EMBED * EMBED;
    __nv_bfloat16* wo_h = (__nv_bfloat16*)p_q;
    __nv_bfloat16* wo_l = wo_h + EMBED * EMBED;
    (void)wq_planes;

    split_w<<<3 * EMBED * EMBED / 1024, 256>>>(qkv_w, wq_h, wq_l);

    // 1) QKV projection: A=x (in-kernel split), B=pre-split planes
    gemm_qkv<<<dim3(3 * EMBED / 128, MTOK / 128), 256, GEMM_SMEM>>>(
        x, wq_h, qkv_b);

    // 2) Flash attention (reads q/k/v planes) -> O hi/lo planes in g_attn
    attn_wmma<<<dim3(SEQ / 128, BATCH * NHEADS), 256, ATTN_SMEM_BYTES>>>();

    // 3) split out_w into g_q (dead after attention), then projection
    split_w<<<EMBED * EMBED / 1024, 256>>>(out_w, wo_h, wo_l);
    gemm_proj<<<dim3(EMBED / 128, MTOK / 128), 256, GEMM_SMEM>>>(
        (const __nv_bfloat16*)p_attn, wo_h, out_b, out);
}